// round 1
// baseline (speedup 1.0000x reference)
#include <cuda_runtime.h>

#define S 2048
#define DM 1024
#define NH 16
#define DK 64
#define BATCH 4
#define ROWS (BATCH*S)   // 8192

// Scratch (device globals: allocation-free per harness rules)
__device__ float g_q[ROWS*DM];                 // [b, s, h*64+dk] == [8192,1024]
__device__ float g_k[ROWS*DM];
__device__ float g_v[ROWS*DM];
__device__ float g_e[(size_t)64*S*S];          // exp(scores), per (b,h): [2048,2048]  (1 GiB)
__device__ float g_part[64*16*S];              // per-rowblock column partial sums
__device__ float g_rz[64*S];                   // 1/colsum
__device__ float g_ctx[ROWS*DM];               // [b, q, h*64+dk]

// ---------------------------------------------------------------------------
// Projection: out[row, h*64+dk] = sum_m X[row,m] * W[h,m,dk] + bias[h*64+dk]
// 128x128 tile, BK=16, 256 threads, 8x8 micro-tile.
// ---------------------------------------------------------------------------
__global__ __launch_bounds__(256) void proj_kernel(const float* __restrict__ X,
                                                   const float* __restrict__ W,
                                                   const float* __restrict__ bias,
                                                   int which)
{
    float* out = (which == 0) ? g_q : (which == 1) ? g_k : g_v;
    __shared__ __align__(16) float As[16][132];
    __shared__ __align__(16) float Bs[16][132];
    const int tid = threadIdx.x;
    const int ty = tid >> 4, tx = tid & 15;
    const int row0 = blockIdx.y << 7;
    const int col0 = blockIdx.x << 7;

    float acc[8][8];
    #pragma unroll
    for (int i = 0; i < 8; i++)
        #pragma unroll
        for (int j = 0; j < 8; j++) acc[i][j] = 0.f;

    for (int k0 = 0; k0 < DM; k0 += 16) {
        #pragma unroll
        for (int i = 0; i < 8; i++) {
            int l = tid + (i << 8);
            int r = l >> 4, kk = l & 15;
            As[kk][r] = X[(size_t)(row0 + r) * DM + k0 + kk];
        }
        #pragma unroll
        for (int i = 0; i < 8; i++) {
            int l = tid + (i << 8);
            int kk = l >> 7, c = l & 127;
            int j = col0 + c;
            Bs[kk][c] = W[((j >> 6) << 16) + ((k0 + kk) << 6) + (j & 63)];
        }
        __syncthreads();
        #pragma unroll
        for (int kk = 0; kk < 16; kk++) {
            float a[8], b[8];
            *(float4*)&a[0] = *(const float4*)&As[kk][ty << 2];
            *(float4*)&a[4] = *(const float4*)&As[kk][64 + (ty << 2)];
            *(float4*)&b[0] = *(const float4*)&Bs[kk][tx << 2];
            *(float4*)&b[4] = *(const float4*)&Bs[kk][64 + (tx << 2)];
            #pragma unroll
            for (int i = 0; i < 8; i++)
                #pragma unroll
                for (int j = 0; j < 8; j++) acc[i][j] += a[i] * b[j];
        }
        __syncthreads();
    }
    float b0[4], b1[4];
    #pragma unroll
    for (int j = 0; j < 4; j++) {
        b0[j] = bias[col0 + (tx << 2) + j];
        b1[j] = bias[col0 + 64 + (tx << 2) + j];
    }
    #pragma unroll
    for (int i = 0; i < 8; i++) {
        int r = row0 + ((i < 4) ? (ty << 2) + i : 64 + (ty << 2) + i - 4);
        float4 o0 = make_float4(acc[i][0] + b0[0], acc[i][1] + b0[1],
                                acc[i][2] + b0[2], acc[i][3] + b0[3]);
        float4 o1 = make_float4(acc[i][4] + b1[0], acc[i][5] + b1[1],
                                acc[i][6] + b1[2], acc[i][7] + b1[3]);
        *(float4*)&out[(size_t)r * DM + col0 + (tx << 2)] = o0;
        *(float4*)&out[(size_t)r * DM + col0 + 64 + (tx << 2)] = o1;
    }
}

// ---------------------------------------------------------------------------
// Scores + exp + deterministic column partial sums.
// Per (b,h): E[q,s] = exp( (q_h[q,:] . k_h[s,:]) / 8 ).  No max subtraction
// needed: |score| <= ~2.  Column sums (over q) written as per-rowblock
// partials (no atomics -> deterministic).
// ---------------------------------------------------------------------------
__global__ __launch_bounds__(256) void scores_kernel()
{
    const int z = blockIdx.z, b = z >> 4, h = z & 15;
    const float* qh = g_q + (size_t)b * S * DM + h * DK;
    const float* kh = g_k + (size_t)b * S * DM + h * DK;
    float* ez = g_e + (size_t)z * S * S;
    __shared__ __align__(16) float As[16][132];
    __shared__ __align__(16) float Bs[16][132];
    __shared__ float red[16][128];
    const int tid = threadIdx.x;
    const int ty = tid >> 4, tx = tid & 15;
    const int row0 = blockIdx.y << 7;   // q
    const int col0 = blockIdx.x << 7;   // s

    float acc[8][8];
    #pragma unroll
    for (int i = 0; i < 8; i++)
        #pragma unroll
        for (int j = 0; j < 8; j++) acc[i][j] = 0.f;

    for (int k0 = 0; k0 < DK; k0 += 16) {
        #pragma unroll
        for (int i = 0; i < 8; i++) {
            int l = tid + (i << 8);
            int r = l >> 4, kk = l & 15;
            As[kk][r] = qh[(size_t)(row0 + r) * DM + k0 + kk];
        }
        #pragma unroll
        for (int i = 0; i < 8; i++) {
            int l = tid + (i << 8);
            int c = l >> 4, kk = l & 15;
            Bs[kk][c] = kh[(size_t)(col0 + c) * DM + k0 + kk];
        }
        __syncthreads();
        #pragma unroll
        for (int kk = 0; kk < 16; kk++) {
            float a[8], bb[8];
            *(float4*)&a[0]  = *(const float4*)&As[kk][ty << 2];
            *(float4*)&a[4]  = *(const float4*)&As[kk][64 + (ty << 2)];
            *(float4*)&bb[0] = *(const float4*)&Bs[kk][tx << 2];
            *(float4*)&bb[4] = *(const float4*)&Bs[kk][64 + (tx << 2)];
            #pragma unroll
            for (int i = 0; i < 8; i++)
                #pragma unroll
                for (int j = 0; j < 8; j++) acc[i][j] += a[i] * bb[j];
        }
        __syncthreads();
    }

    float csum[8];
    #pragma unroll
    for (int j = 0; j < 8; j++) csum[j] = 0.f;

    #pragma unroll
    for (int i = 0; i < 8; i++) {
        int r = row0 + ((i < 4) ? (ty << 2) + i : 64 + (ty << 2) + i - 4);
        float e[8];
        #pragma unroll
        for (int j = 0; j < 8; j++) {
            e[j] = __expf(acc[i][j] * 0.125f);
            csum[j] += e[j];
        }
        *(float4*)&ez[(size_t)r * S + col0 + (tx << 2)] =
            make_float4(e[0], e[1], e[2], e[3]);
        *(float4*)&ez[(size_t)r * S + col0 + 64 + (tx << 2)] =
            make_float4(e[4], e[5], e[6], e[7]);
    }
    #pragma unroll
    for (int j = 0; j < 4; j++) {
        red[ty][(tx << 2) + j]      = csum[j];
    }
    #pragma unroll
    for (int j = 4; j < 8; j++) {
        red[ty][64 + (tx << 2) + j - 4] = csum[j];
    }
    __syncthreads();
    if (tid < 128) {
        float s = 0.f;
        #pragma unroll
        for (int t = 0; t < 16; t++) s += red[t][tid];
        g_part[((size_t)z * 16 + blockIdx.y) * S + col0 + tid] = s;
    }
}

// Reduce the 16 row-block partials per column and take the reciprocal.
__global__ __launch_bounds__(256) void recip_kernel()
{
    int i = blockIdx.x * 256 + threadIdx.x;   // over 64*2048
    int z = i >> 11, c = i & 2047;
    float s = 0.f;
    #pragma unroll
    for (int t = 0; t < 16; t++) s += g_part[((size_t)z * 16 + t) * S + c];
    g_rz[i] = 1.0f / s;
}

// ---------------------------------------------------------------------------
// ctx[q, dk] = sum_s E[q,s] * (V[s,dk] / Z[s]).  Per (b,h): 2048x64x2048.
// BM=128, BN=64, BK=32; 1/Z folded into the V-tile load.
// Output written in concat layout [b, q, h*64+dk].
// ---------------------------------------------------------------------------
__global__ __launch_bounds__(256) void ctx_kernel()
{
    const int z = blockIdx.z, b = z >> 4, h = z & 15;
    const float* ez = g_e + (size_t)z * S * S;
    const float* vh = g_v + (size_t)b * S * DM + h * DK;
    const float* rz = g_rz + z * S;
    const int tid = threadIdx.x;
    const int ty = tid >> 4, tx = tid & 15;
    const int row0 = blockIdx.y << 7;
    __shared__ __align__(16) float As[32][132];
    __shared__ __align__(16) float Bs[32][68];

    float acc[8][4];
    #pragma unroll
    for (int i = 0; i < 8; i++)
        #pragma unroll
        for (int j = 0; j < 4; j++) acc[i][j] = 0.f;

    for (int s0 = 0; s0 < S; s0 += 32) {
        #pragma unroll
        for (int i = 0; i < 16; i++) {
            int l = tid + (i << 8);
            int r = l >> 5, kk = l & 31;
            As[kk][r] = ez[(size_t)(row0 + r) * S + s0 + kk];
        }
        #pragma unroll
        for (int i = 0; i < 8; i++) {
            int l = tid + (i << 8);
            int kk = l >> 6, c = l & 63;
            Bs[kk][c] = vh[(size_t)(s0 + kk) * DM + c] * rz[s0 + kk];
        }
        __syncthreads();
        #pragma unroll
        for (int kk = 0; kk < 32; kk++) {
            float a[8], bb[4];
            *(float4*)&a[0]  = *(const float4*)&As[kk][ty << 2];
            *(float4*)&a[4]  = *(const float4*)&As[kk][64 + (ty << 2)];
            *(float4*)&bb[0] = *(const float4*)&Bs[kk][tx << 2];
            #pragma unroll
            for (int i = 0; i < 8; i++)
                #pragma unroll
                for (int j = 0; j < 4; j++) acc[i][j] += a[i] * bb[j];
        }
        __syncthreads();
    }
    #pragma unroll
    for (int i = 0; i < 8; i++) {
        int r = row0 + ((i < 4) ? (ty << 2) + i : 64 + (ty << 2) + i - 4);
        *(float4*)&g_ctx[((size_t)b * S + r) * DM + h * DK + (tx << 2)] =
            make_float4(acc[i][0], acc[i][1], acc[i][2], acc[i][3]);
    }
}

// ---------------------------------------------------------------------------
// out[row, n] = sum_m ctx[row, m] * Wo[n, m] + bo[n]   (out = ctx @ Wo^T + bo)
// ---------------------------------------------------------------------------
__global__ __launch_bounds__(256) void out_kernel(const float* __restrict__ Wo,
                                                  const float* __restrict__ bo,
                                                  float* __restrict__ out)
{
    __shared__ __align__(16) float As[16][132];
    __shared__ __align__(16) float Bs[16][132];
    const int tid = threadIdx.x;
    const int ty = tid >> 4, tx = tid & 15;
    const int row0 = blockIdx.y << 7;
    const int col0 = blockIdx.x << 7;

    float acc[8][8];
    #pragma unroll
    for (int i = 0; i < 8; i++)
        #pragma unroll
        for (int j = 0; j < 8; j++) acc[i][j] = 0.f;

    for (int k0 = 0; k0 < DM; k0 += 16) {
        #pragma unroll
        for (int i = 0; i < 8; i++) {
            int l = tid + (i << 8);
            int r = l >> 4, kk = l & 15;
            As[kk][r] = g_ctx[(size_t)(row0 + r) * DM + k0 + kk];
        }
        #pragma unroll
        for (int i = 0; i < 8; i++) {
            int l = tid + (i << 8);
            int c = l >> 4, kk = l & 15;
            Bs[kk][c] = Wo[(size_t)(col0 + c) * DM + k0 + kk];
        }
        __syncthreads();
        #pragma unroll
        for (int kk = 0; kk < 16; kk++) {
            float a[8], b[8];
            *(float4*)&a[0] = *(const float4*)&As[kk][ty << 2];
            *(float4*)&a[4] = *(const float4*)&As[kk][64 + (ty << 2)];
            *(float4*)&b[0] = *(const float4*)&Bs[kk][tx << 2];
            *(float4*)&b[4] = *(const float4*)&Bs[kk][64 + (tx << 2)];
            #pragma unroll
            for (int i = 0; i < 8; i++)
                #pragma unroll
                for (int j = 0; j < 8; j++) acc[i][j] += a[i] * b[j];
        }
        __syncthreads();
    }
    float b0[4], b1[4];
    #pragma unroll
    for (int j = 0; j < 4; j++) {
        b0[j] = bo[col0 + (tx << 2) + j];
        b1[j] = bo[col0 + 64 + (tx << 2) + j];
    }
    #pragma unroll
    for (int i = 0; i < 8; i++) {
        int r = row0 + ((i < 4) ? (ty << 2) + i : 64 + (ty << 2) + i - 4);
        float4 o0 = make_float4(acc[i][0] + b0[0], acc[i][1] + b0[1],
                                acc[i][2] + b0[2], acc[i][3] + b0[3]);
        float4 o1 = make_float4(acc[i][4] + b1[0], acc[i][5] + b1[1],
                                acc[i][6] + b1[2], acc[i][7] + b1[3]);
        *(float4*)&out[(size_t)r * DM + col0 + (tx << 2)] = o0;
        *(float4*)&out[(size_t)r * DM + col0 + 64 + (tx << 2)] = o1;
    }
}

extern "C" void kernel_launch(void* const* d_in, const int* in_sizes, int n_in,
                              void* d_out, int out_size)
{
    const float* query = (const float*)d_in[0];
    const float* key_  = (const float*)d_in[1];
    const float* value = (const float*)d_in[2];
    const float* Wq    = (const float*)d_in[3];
    const float* bq    = (const float*)d_in[4];
    const float* Wk    = (const float*)d_in[5];
    const float* bk    = (const float*)d_in[6];
    const float* Wv    = (const float*)d_in[7];
    const float* bv    = (const float*)d_in[8];
    const float* Wo    = (const float*)d_in[9];
    const float* bo    = (const float*)d_in[10];
    float* out = (float*)d_out;

    dim3 g1(8, 64);
    proj_kernel<<<g1, 256>>>(query, Wq, bq, 0);
    proj_kernel<<<g1, 256>>>(key_,  Wk, bk, 1);
    proj_kernel<<<g1, 256>>>(value, Wv, bv, 2);
    scores_kernel<<<dim3(16, 16, 64), 256>>>();
    recip_kernel<<<512, 256>>>();
    ctx_kernel<<<dim3(1, 16, 64), 256>>>();
    out_kernel<<<g1, 256>>>(Wo, bo, out);
}

// round 2
// speedup vs baseline: 2.8422x; 2.8422x over previous
#include <cuda_runtime.h>

#define DM 1024

// Scratch (device globals: allocation-free per harness rules)
__device__ float    g_q[8192 * 1024];
__device__ float    g_k[8192 * 1024];
__device__ float    g_v[8192 * 1024];
__device__ unsigned g_vt[64 * 64 * 1024];   // V^T per (b,h): [dk=64][s=2048] as fp16x2 words
__device__ float    g_rz[64 * 2048];        // 1 / column-sum (softmax over query axis)
__device__ float    g_ctx[8192 * 1024];

// ---------------------------------------------------------------------------
// helpers
// ---------------------------------------------------------------------------
__device__ __forceinline__ unsigned f2tf(float x) {
    unsigned r; asm("cvt.rna.tf32.f32 %0, %1;" : "=r"(r) : "f"(x)); return r;
}
__device__ __forceinline__ unsigned packh2(float lo, float hi) {
    unsigned r; asm("cvt.rn.f16x2.f32 %0, %1, %2;" : "=r"(r) : "f"(hi), "f"(lo)); return r;
}
__device__ __forceinline__ void mma_tf32(float* c, const unsigned* a, const unsigned* b) {
    asm volatile("mma.sync.aligned.m16n8k8.row.col.f32.tf32.tf32.f32 "
        "{%0,%1,%2,%3},{%4,%5,%6,%7},{%8,%9},{%0,%1,%2,%3};"
        : "+f"(c[0]), "+f"(c[1]), "+f"(c[2]), "+f"(c[3])
        : "r"(a[0]), "r"(a[1]), "r"(a[2]), "r"(a[3]), "r"(b[0]), "r"(b[1]));
}
__device__ __forceinline__ void mma_f16(float* c, const unsigned* a, const unsigned* b) {
    asm volatile("mma.sync.aligned.m16n8k16.row.col.f32.f16.f16.f32 "
        "{%0,%1,%2,%3},{%4,%5,%6,%7},{%8,%9},{%0,%1,%2,%3};"
        : "+f"(c[0]), "+f"(c[1]), "+f"(c[2]), "+f"(c[3])
        : "r"(a[0]), "r"(a[1]), "r"(a[2]), "r"(a[3]), "r"(b[0]), "r"(b[1]));
}

// ---------------------------------------------------------------------------
// Projections: out[row, h*64+dk] = sum_m X[row,m] * W[h,m,dk] + bias
// 128x128 block tile, BK=32, 8 warps (2x4), warp tile 64x32, tf32 mma.
// ---------------------------------------------------------------------------
__global__ __launch_bounds__(256) void proj_mma(
    const float* __restrict__ Xq, const float* __restrict__ Xk, const float* __restrict__ Xv,
    const float* __restrict__ Wq, const float* __restrict__ Wk, const float* __restrict__ Wv,
    const float* __restrict__ bq, const float* __restrict__ bk, const float* __restrict__ bv)
{
    const int zc = blockIdx.z;
    const float* X    = (zc == 0) ? Xq : (zc == 1) ? Xk : Xv;
    const float* W    = (zc == 0) ? Wq : (zc == 1) ? Wk : Wv;
    const float* bias = (zc == 0) ? bq : (zc == 1) ? bk : bv;
    float* out        = (zc == 0) ? g_q : (zc == 1) ? g_k : g_v;

    __shared__ __align__(16) unsigned As[128][36];   // [m][k]
    __shared__ __align__(16) unsigned Bs[32][132];   // [k][n]
    const int tid = threadIdx.x, lane = tid & 31, warp = tid >> 5;
    const int wm = warp >> 2, wn = warp & 3;
    const int row0 = blockIdx.y << 7, col0 = blockIdx.x << 7;

    float acc[4][4][4];
    #pragma unroll
    for (int i = 0; i < 4; i++)
        #pragma unroll
        for (int j = 0; j < 4; j++)
            #pragma unroll
            for (int k = 0; k < 4; k++) acc[i][j][k] = 0.f;

    for (int k0 = 0; k0 < DM; k0 += 32) {
        #pragma unroll
        for (int i = 0; i < 4; i++) {
            int idx = tid + (i << 8);
            int r = idx >> 3, j = (idx & 7) << 2;
            float4 v = *(const float4*)&X[(size_t)(row0 + r) * DM + k0 + j];
            *(uint4*)&As[r][j] = make_uint4(f2tf(v.x), f2tf(v.y), f2tf(v.z), f2tf(v.w));
        }
        #pragma unroll
        for (int i = 0; i < 4; i++) {
            int idx = tid + (i << 8);
            int k = idx >> 5, n = (idx & 31) << 2;
            int col = col0 + n;
            float4 v = *(const float4*)&W[((col >> 6) << 16) + ((k0 + k) << 6) + (col & 63)];
            *(uint4*)&Bs[k][n] = make_uint4(f2tf(v.x), f2tf(v.y), f2tf(v.z), f2tf(v.w));
        }
        __syncthreads();
        #pragma unroll
        for (int ks = 0; ks < 4; ks++) {
            const int kb = (ks << 3) + (lane & 3), rb = lane >> 2;
            unsigned a[4][4], bf[4][2];
            #pragma unroll
            for (int fm = 0; fm < 4; fm++) {
                int m = (wm << 6) + (fm << 4) + rb;
                a[fm][0] = As[m][kb];     a[fm][1] = As[m + 8][kb];
                a[fm][2] = As[m][kb + 4]; a[fm][3] = As[m + 8][kb + 4];
            }
            #pragma unroll
            for (int fn = 0; fn < 4; fn++) {
                int n = (wn << 5) + (fn << 3) + rb;
                bf[fn][0] = Bs[kb][n]; bf[fn][1] = Bs[kb + 4][n];
            }
            #pragma unroll
            for (int fm = 0; fm < 4; fm++)
                #pragma unroll
                for (int fn = 0; fn < 4; fn++)
                    mma_tf32(acc[fm][fn], a[fm], bf[fn]);
        }
        __syncthreads();
    }
    #pragma unroll
    for (int fn = 0; fn < 4; fn++) {
        int c = col0 + (wn << 5) + (fn << 3) + ((lane & 3) << 1);
        float b0 = bias[c], b1 = bias[c + 1];
        #pragma unroll
        for (int fm = 0; fm < 4; fm++) {
            int r = row0 + (wm << 6) + (fm << 4) + (lane >> 2);
            *(float2*)&out[(size_t)r * DM + c] =
                make_float2(acc[fm][fn][0] + b0, acc[fm][fn][1] + b1);
            *(float2*)&out[(size_t)(r + 8) * DM + c] =
                make_float2(acc[fm][fn][2] + b0, acc[fm][fn][3] + b1);
        }
    }
}

// ---------------------------------------------------------------------------
// V -> fp16 transposed: g_vt[z][dk][s]  (half2 words along s)
// ---------------------------------------------------------------------------
__global__ __launch_bounds__(256) void v2h_kernel()
{
    __shared__ float T[64][68];
    const int tid = threadIdx.x;
    const int z = blockIdx.y, b = z >> 4, h = z & 15;
    const int s0 = blockIdx.x << 6;
    const float* vh = g_v + (size_t)b * 2048 * DM + h * 64;
    #pragma unroll
    for (int i = 0; i < 4; i++) {
        int idx = tid + (i << 8);
        int s = idx >> 4, j = (idx & 15) << 2;
        *(float4*)&T[s][j] = *(const float4*)&vh[(size_t)(s0 + s) * DM + j];
    }
    __syncthreads();
    unsigned* outp = g_vt + (size_t)z * 64 * 1024;
    #pragma unroll
    for (int i = 0; i < 4; i++) {
        int idx = tid + (i << 8);
        int dk = idx >> 4, sj = (idx & 15) << 2;
        uint2 u;
        u.x = packh2(T[sj][dk],     T[sj + 1][dk]);
        u.y = packh2(T[sj + 2][dk], T[sj + 3][dk]);
        *(uint2*)&outp[dk * 1024 + ((s0 + sj) >> 1)] = u;
    }
}

// ---------------------------------------------------------------------------
// Pass 1: column sums of E = exp(QK^T/8) over the query axis -> g_rz = 1/Z.
// Block owns a 128-wide s-tile of one (b,h); loops over all q in 128-chunks.
// 8 warps (2x4), warp tile 64q x 32s, tf32 mma, K=64.
// ---------------------------------------------------------------------------
__global__ __launch_bounds__(256) void colsum_mma()
{
    extern __shared__ __align__(16) unsigned dsm[];
    unsigned (*As)[68] = (unsigned(*)[68])dsm;                 // q-tile [128][68]
    unsigned (*Bs)[68] = (unsigned(*)[68])(dsm + 128 * 68);    // k-tile [128][68] (s-major)
    float (*red)[128]  = (float(*)[128])(dsm + 2 * 128 * 68);  // [16][128]

    const int tid = threadIdx.x, lane = tid & 31, warp = tid >> 5;
    const int wm = warp >> 2, wn = warp & 3;
    const int z = blockIdx.y, b = z >> 4, h = z & 15;
    const int s0 = blockIdx.x << 7;
    const float* qh = g_q + (size_t)b * 2048 * DM + h * 64;
    const float* kh = g_k + (size_t)b * 2048 * DM + h * 64;

    #pragma unroll
    for (int i = 0; i < 8; i++) {
        int idx = tid + (i << 8);
        int r = idx >> 4, j = (idx & 15) << 2;
        float4 v = *(const float4*)&kh[(size_t)(s0 + r) * DM + j];
        *(uint4*)&Bs[r][j] = make_uint4(f2tf(v.x), f2tf(v.y), f2tf(v.z), f2tf(v.w));
    }
    float colacc[8];
    #pragma unroll
    for (int i = 0; i < 8; i++) colacc[i] = 0.f;
    __syncthreads();

    for (int it = 0; it < 16; it++) {
        const int q0 = it << 7;
        #pragma unroll
        for (int i = 0; i < 8; i++) {
            int idx = tid + (i << 8);
            int r = idx >> 4, j = (idx & 15) << 2;
            float4 v = *(const float4*)&qh[(size_t)(q0 + r) * DM + j];
            *(uint4*)&As[r][j] = make_uint4(f2tf(v.x), f2tf(v.y), f2tf(v.z), f2tf(v.w));
        }
        __syncthreads();
        float acc[4][4][4];
        #pragma unroll
        for (int i = 0; i < 4; i++)
            #pragma unroll
            for (int j = 0; j < 4; j++)
                #pragma unroll
                for (int k = 0; k < 4; k++) acc[i][j][k] = 0.f;
        #pragma unroll
        for (int ks = 0; ks < 8; ks++) {
            const int kb = (ks << 3) + (lane & 3), rb = lane >> 2;
            unsigned a[4][4], bf[4][2];
            #pragma unroll
            for (int fm = 0; fm < 4; fm++) {
                int m = (wm << 6) + (fm << 4) + rb;
                a[fm][0] = As[m][kb];     a[fm][1] = As[m + 8][kb];
                a[fm][2] = As[m][kb + 4]; a[fm][3] = As[m + 8][kb + 4];
            }
            #pragma unroll
            for (int fn = 0; fn < 4; fn++) {
                int n = (wn << 5) + (fn << 3) + rb;
                bf[fn][0] = Bs[n][kb]; bf[fn][1] = Bs[n][kb + 4];
            }
            #pragma unroll
            for (int fm = 0; fm < 4; fm++)
                #pragma unroll
                for (int fn = 0; fn < 4; fn++)
                    mma_tf32(acc[fm][fn], a[fm], bf[fn]);
        }
        #pragma unroll
        for (int fm = 0; fm < 4; fm++)
            #pragma unroll
            for (int fn = 0; fn < 4; fn++) {
                colacc[2 * fn]     += __expf(acc[fm][fn][0] * 0.125f) + __expf(acc[fm][fn][2] * 0.125f);
                colacc[2 * fn + 1] += __expf(acc[fm][fn][1] * 0.125f) + __expf(acc[fm][fn][3] * 0.125f);
            }
        __syncthreads();
    }
    const int rg = (wm << 3) + (lane >> 2);
    #pragma unroll
    for (int fn = 0; fn < 4; fn++) {
        int c = (wn << 5) + (fn << 3) + ((lane & 3) << 1);
        red[rg][c]     = colacc[2 * fn];
        red[rg][c + 1] = colacc[2 * fn + 1];
    }
    __syncthreads();
    if (tid < 128) {
        float s = 0.f;
        #pragma unroll
        for (int t = 0; t < 16; t++) s += red[t][tid];
        g_rz[z * 2048 + s0 + tid] = 1.0f / s;
    }
}

// ---------------------------------------------------------------------------
// Pass 2: fused scores-recompute + softmax-apply + P@V (flash-style).
// Block owns a 128-q tile of one (b,h); loops over 16 s-tiles of 128.
// 8 warps (4 q-groups x 2 s-halves); warp: 32q x 64s scores (tf32),
// then 32q x 64dk ctx partial over its 64-s slice (fp16 mma, FA2 frag reuse).
// Cross-half reduction at the end through smem.
// ---------------------------------------------------------------------------
__global__ __launch_bounds__(256) void ctx_mma()
{
    extern __shared__ __align__(16) unsigned dsm[];
    unsigned (*Aq)[68] = (unsigned(*)[68])dsm;                  // [128][68]
    unsigned (*Ks)[68] = (unsigned(*)[68])(dsm + 8704);         // [128][68]
    unsigned (*Vs)[68] = (unsigned(*)[68])(dsm + 17408);        // [64][68] half2 words
    float* rzs = (float*)(dsm + 17408 + 64 * 68);               // [128]
    float* buf = (float*)(dsm + 8704);                          // reuse Ks: [128*64]

    const int tid = threadIdx.x, lane = tid & 31, warp = tid >> 5;
    const int wm = warp >> 1, ws = warp & 1;
    const int z = blockIdx.y, b = z >> 4, h = z & 15;
    const int q0 = blockIdx.x << 7;
    const float* qh = g_q + (size_t)b * 2048 * DM + h * 64;
    const float* kh = g_k + (size_t)b * 2048 * DM + h * 64;
    const unsigned* vt = g_vt + (size_t)z * 64 * 1024;

    #pragma unroll
    for (int i = 0; i < 8; i++) {
        int idx = tid + (i << 8);
        int r = idx >> 4, j = (idx & 15) << 2;
        float4 v = *(const float4*)&qh[(size_t)(q0 + r) * DM + j];
        *(uint4*)&Aq[r][j] = make_uint4(f2tf(v.x), f2tf(v.y), f2tf(v.z), f2tf(v.w));
    }
    float cacc[2][8][4];
    #pragma unroll
    for (int i = 0; i < 2; i++)
        #pragma unroll
        for (int j = 0; j < 8; j++)
            #pragma unroll
            for (int k = 0; k < 4; k++) cacc[i][j][k] = 0.f;

    for (int it = 0; it < 16; it++) {
        const int s0 = it << 7;
        __syncthreads();
        #pragma unroll
        for (int i = 0; i < 8; i++) {
            int idx = tid + (i << 8);
            int r = idx >> 4, j = (idx & 15) << 2;
            float4 v = *(const float4*)&kh[(size_t)(s0 + r) * DM + j];
            *(uint4*)&Ks[r][j] = make_uint4(f2tf(v.x), f2tf(v.y), f2tf(v.z), f2tf(v.w));
        }
        #pragma unroll
        for (int i = 0; i < 4; i++) {
            int idx = tid + (i << 8);
            int dk = idx >> 4, w4 = (idx & 15) << 2;
            *(uint4*)&Vs[dk][w4] = *(const uint4*)&vt[dk * 1024 + (s0 >> 1) + w4];
        }
        if (tid < 128) rzs[tid] = g_rz[z * 2048 + s0 + tid];
        __syncthreads();

        float sacc[2][8][4];
        #pragma unroll
        for (int i = 0; i < 2; i++)
            #pragma unroll
            for (int j = 0; j < 8; j++)
                #pragma unroll
                for (int k = 0; k < 4; k++) sacc[i][j][k] = 0.f;

        #pragma unroll
        for (int ks = 0; ks < 8; ks++) {
            const int kb = (ks << 3) + (lane & 3), rb = lane >> 2;
            unsigned a[2][4], bf[8][2];
            #pragma unroll
            for (int fm = 0; fm < 2; fm++) {
                int m = (wm << 5) + (fm << 4) + rb;
                a[fm][0] = Aq[m][kb];     a[fm][1] = Aq[m + 8][kb];
                a[fm][2] = Aq[m][kb + 4]; a[fm][3] = Aq[m + 8][kb + 4];
            }
            #pragma unroll
            for (int fn = 0; fn < 8; fn++) {
                int n = (ws << 6) + (fn << 3) + rb;
                bf[fn][0] = Ks[n][kb]; bf[fn][1] = Ks[n][kb + 4];
            }
            #pragma unroll
            for (int fm = 0; fm < 2; fm++)
                #pragma unroll
                for (int fn = 0; fn < 8; fn++)
                    mma_tf32(sacc[fm][fn], a[fm], bf[fn]);
        }
        // P = exp(score/8) * rz[s]; fused P@V in fp16 (C-frag -> A-frag identity)
        #pragma unroll
        for (int j = 0; j < 4; j++) {
            const int cA = (ws << 6) + (j << 4) + ((lane & 3) << 1);
            const float rA0 = rzs[cA], rA1 = rzs[cA + 1];
            const float rB0 = rzs[cA + 8], rB1 = rzs[cA + 9];
            unsigned pa[2][4];
            #pragma unroll
            for (int fm = 0; fm < 2; fm++) {
                const float* sA = sacc[fm][2 * j];
                const float* sB = sacc[fm][2 * j + 1];
                pa[fm][0] = packh2(__expf(sA[0] * 0.125f) * rA0, __expf(sA[1] * 0.125f) * rA1);
                pa[fm][1] = packh2(__expf(sA[2] * 0.125f) * rA0, __expf(sA[3] * 0.125f) * rA1);
                pa[fm][2] = packh2(__expf(sB[0] * 0.125f) * rB0, __expf(sB[1] * 0.125f) * rB1);
                pa[fm][3] = packh2(__expf(sB[2] * 0.125f) * rB0, __expf(sB[3] * 0.125f) * rB1);
            }
            const int kw = (ws << 5) + (j << 3) + (lane & 3);
            #pragma unroll
            for (int fb = 0; fb < 8; fb++) {
                int n = (fb << 3) + (lane >> 2);
                unsigned bb[2] = { Vs[n][kw], Vs[n][kw + 4] };
                #pragma unroll
                for (int fm = 0; fm < 2; fm++)
                    mma_f16(cacc[fm][fb], pa[fm], bb);
            }
        }
    }
    __syncthreads();
    if (ws == 1) {
        #pragma unroll
        for (int fm = 0; fm < 2; fm++)
            #pragma unroll
            for (int fb = 0; fb < 8; fb++) {
                int q = (wm << 5) + (fm << 4) + (lane >> 2);
                int dk = (fb << 3) + ((lane & 3) << 1);
                *(float2*)&buf[q * 64 + dk]       = make_float2(cacc[fm][fb][0], cacc[fm][fb][1]);
                *(float2*)&buf[(q + 8) * 64 + dk] = make_float2(cacc[fm][fb][2], cacc[fm][fb][3]);
            }
    }
    __syncthreads();
    if (ws == 0) {
        float* outp = g_ctx + (size_t)b * 2048 * DM + h * 64;
        #pragma unroll
        for (int fm = 0; fm < 2; fm++)
            #pragma unroll
            for (int fb = 0; fb < 8; fb++) {
                int q = (wm << 5) + (fm << 4) + (lane >> 2);
                int dk = (fb << 3) + ((lane & 3) << 1);
                float2 p0 = *(float2*)&buf[q * 64 + dk];
                float2 p1 = *(float2*)&buf[(q + 8) * 64 + dk];
                *(float2*)&outp[(size_t)(q0 + q) * DM + dk] =
                    make_float2(cacc[fm][fb][0] + p0.x, cacc[fm][fb][1] + p0.y);
                *(float2*)&outp[(size_t)(q0 + q + 8) * DM + dk] =
                    make_float2(cacc[fm][fb][2] + p1.x, cacc[fm][fb][3] + p1.y);
            }
    }
}

// ---------------------------------------------------------------------------
// out = ctx @ Wo^T + bo ; same skeleton as proj, B comes from Wo[n, k].
// ---------------------------------------------------------------------------
__global__ __launch_bounds__(256) void out_mma(const float* __restrict__ Wo,
                                               const float* __restrict__ bo,
                                               float* __restrict__ out)
{
    __shared__ __align__(16) unsigned As[128][36];   // [m][k]
    __shared__ __align__(16) unsigned Bs[128][36];   // [n][k]
    const int tid = threadIdx.x, lane = tid & 31, warp = tid >> 5;
    const int wm = warp >> 2, wn = warp & 3;
    const int row0 = blockIdx.y << 7, col0 = blockIdx.x << 7;

    float acc[4][4][4];
    #pragma unroll
    for (int i = 0; i < 4; i++)
        #pragma unroll
        for (int j = 0; j < 4; j++)
            #pragma unroll
            for (int k = 0; k < 4; k++) acc[i][j][k] = 0.f;

    for (int k0 = 0; k0 < DM; k0 += 32) {
        #pragma unroll
        for (int i = 0; i < 4; i++) {
            int idx = tid + (i << 8);
            int r = idx >> 3, j = (idx & 7) << 2;
            float4 v = *(const float4*)&g_ctx[(size_t)(row0 + r) * DM + k0 + j];
            *(uint4*)&As[r][j] = make_uint4(f2tf(v.x), f2tf(v.y), f2tf(v.z), f2tf(v.w));
        }
        #pragma unroll
        for (int i = 0; i < 4; i++) {
            int idx = tid + (i << 8);
            int n = idx >> 3, j = (idx & 7) << 2;
            float4 v = *(const float4*)&Wo[(size_t)(col0 + n) * DM + k0 + j];
            *(uint4*)&Bs[n][j] = make_uint4(f2tf(v.x), f2tf(v.y), f2tf(v.z), f2tf(v.w));
        }
        __syncthreads();
        #pragma unroll
        for (int ks = 0; ks < 4; ks++) {
            const int kb = (ks << 3) + (lane & 3), rb = lane >> 2;
            unsigned a[4][4], bf[4][2];
            #pragma unroll
            for (int fm = 0; fm < 4; fm++) {
                int m = (wm << 6) + (fm << 4) + rb;
                a[fm][0] = As[m][kb];     a[fm][1] = As[m + 8][kb];
                a[fm][2] = As[m][kb + 4]; a[fm][3] = As[m + 8][kb + 4];
            }
            #pragma unroll
            for (int fn = 0; fn < 4; fn++) {
                int n = (wn << 5) + (fn << 3) + rb;
                bf[fn][0] = Bs[n][kb]; bf[fn][1] = Bs[n][kb + 4];
            }
            #pragma unroll
            for (int fm = 0; fm < 4; fm++)
                #pragma unroll
                for (int fn = 0; fn < 4; fn++)
                    mma_tf32(acc[fm][fn], a[fm], bf[fn]);
        }
        __syncthreads();
    }
    #pragma unroll
    for (int fn = 0; fn < 4; fn++) {
        int c = col0 + (wn << 5) + (fn << 3) + ((lane & 3) << 1);
        float b0 = bo[c], b1 = bo[c + 1];
        #pragma unroll
        for (int fm = 0; fm < 4; fm++) {
            int r = row0 + (wm << 6) + (fm << 4) + (lane >> 2);
            *(float2*)&out[(size_t)r * DM + c] =
                make_float2(acc[fm][fn][0] + b0, acc[fm][fn][1] + b1);
            *(float2*)&out[(size_t)(r + 8) * DM + c] =
                make_float2(acc[fm][fn][2] + b0, acc[fm][fn][3] + b1);
        }
    }
}

extern "C" void kernel_launch(void* const* d_in, const int* in_sizes, int n_in,
                              void* d_out, int out_size)
{
    const float* query = (const float*)d_in[0];
    const float* key_  = (const float*)d_in[1];
    const float* value = (const float*)d_in[2];
    const float* Wq    = (const float*)d_in[3];
    const float* bq    = (const float*)d_in[4];
    const float* Wk    = (const float*)d_in[5];
    const float* bk    = (const float*)d_in[6];
    const float* Wv    = (const float*)d_in[7];
    const float* bv    = (const float*)d_in[8];
    const float* Wo    = (const float*)d_in[9];
    const float* bo    = (const float*)d_in[10];
    float* out = (float*)d_out;

    cudaFuncSetAttribute(colsum_mma, cudaFuncAttributeMaxDynamicSharedMemorySize, 77824);
    cudaFuncSetAttribute(ctx_mma,    cudaFuncAttributeMaxDynamicSharedMemorySize, 87552);

    proj_mma<<<dim3(8, 64, 3), 256>>>(query, key_, value, Wq, Wk, Wv, bq, bk, bv);
    v2h_kernel<<<dim3(32, 64), 256>>>();
    colsum_mma<<<dim3(16, 64), 256, 77824>>>();
    ctx_mma<<<dim3(16, 64), 256, 87552>>>();
    out_mma<<<dim3(8, 64), 256>>>(Wo, bo, out);
}

// round 3
// speedup vs baseline: 3.3832x; 1.1903x over previous
#include <cuda_runtime.h>
#include <cuda_fp16.h>

#define DM 1024

// Scratch (device globals: allocation-free per harness rules)
__device__ float  g_q[8192 * 1024];
__device__ float  g_k[8192 * 1024];
__device__ float  g_v[8192 * 1024];
__device__ __half g_eh[(size_t)64 * 2048 * 2048];  // E = exp(scores) fp16, per (b,h)  (512 MiB)
__device__ float  g_part[64 * 16 * 2048];          // per-qtile column partial sums
__device__ float  g_rz[64 * 2048];                 // 1 / column-sum (softmax over query axis)
__device__ __half g_vt[(size_t)64 * 64 * 2048];    // V'^T fp16 [z][dk][s], rz folded in
__device__ float  g_ctx[8192 * 1024];

// ---------------------------------------------------------------------------
// helpers
// ---------------------------------------------------------------------------
__device__ __forceinline__ unsigned f2tf(float x) {
    unsigned r; asm("cvt.rna.tf32.f32 %0, %1;" : "=r"(r) : "f"(x)); return r;
}
__device__ __forceinline__ unsigned packh2(float lo, float hi) {
    unsigned r; asm("cvt.rn.f16x2.f32 %0, %1, %2;" : "=r"(r) : "f"(hi), "f"(lo)); return r;
}
__device__ __forceinline__ void mma_tf32(float* c, const unsigned* a, const unsigned* b) {
    asm volatile("mma.sync.aligned.m16n8k8.row.col.f32.tf32.tf32.f32 "
        "{%0,%1,%2,%3},{%4,%5,%6,%7},{%8,%9},{%0,%1,%2,%3};"
        : "+f"(c[0]), "+f"(c[1]), "+f"(c[2]), "+f"(c[3])
        : "r"(a[0]), "r"(a[1]), "r"(a[2]), "r"(a[3]), "r"(b[0]), "r"(b[1]));
}
__device__ __forceinline__ void mma_f16(float* c, const unsigned* a, const unsigned* b) {
    asm volatile("mma.sync.aligned.m16n8k16.row.col.f32.f16.f16.f32 "
        "{%0,%1,%2,%3},{%4,%5,%6,%7},{%8,%9},{%0,%1,%2,%3};"
        : "+f"(c[0]), "+f"(c[1]), "+f"(c[2]), "+f"(c[3])
        : "r"(a[0]), "r"(a[1]), "r"(a[2]), "r"(a[3]), "r"(b[0]), "r"(b[1]));
}
__device__ __forceinline__ void cp16(void* dst, const void* src) {
    unsigned d = (unsigned)__cvta_generic_to_shared(dst);
    asm volatile("cp.async.ca.shared.global [%0], [%1], 16;\n" :: "r"(d), "l"(src));
}

// ---------------------------------------------------------------------------
// Projections: out[row, h*64+dk] = sum_m X[row,m] * W[h,m,dk] + bias
// 128x128 block tile, BK=32, 8 warps (2x4), warp tile 64x32, tf32 mma.
// ---------------------------------------------------------------------------
__global__ __launch_bounds__(256) void proj_mma(
    const float* __restrict__ Xq, const float* __restrict__ Xk, const float* __restrict__ Xv,
    const float* __restrict__ Wq, const float* __restrict__ Wk, const float* __restrict__ Wv,
    const float* __restrict__ bq, const float* __restrict__ bk, const float* __restrict__ bv)
{
    const int zc = blockIdx.z;
    const float* X    = (zc == 0) ? Xq : (zc == 1) ? Xk : Xv;
    const float* W    = (zc == 0) ? Wq : (zc == 1) ? Wk : Wv;
    const float* bias = (zc == 0) ? bq : (zc == 1) ? bk : bv;
    float* out        = (zc == 0) ? g_q : (zc == 1) ? g_k : g_v;

    __shared__ __align__(16) unsigned As[128][36];   // [m][k]
    __shared__ __align__(16) unsigned Bs[32][132];   // [k][n]
    const int tid = threadIdx.x, lane = tid & 31, warp = tid >> 5;
    const int wm = warp >> 2, wn = warp & 3;
    const int row0 = blockIdx.y << 7, col0 = blockIdx.x << 7;

    float acc[4][4][4];
    #pragma unroll
    for (int i = 0; i < 4; i++)
        #pragma unroll
        for (int j = 0; j < 4; j++)
            #pragma unroll
            for (int k = 0; k < 4; k++) acc[i][j][k] = 0.f;

    for (int k0 = 0; k0 < DM; k0 += 32) {
        #pragma unroll
        for (int i = 0; i < 4; i++) {
            int idx = tid + (i << 8);
            int r = idx >> 3, j = (idx & 7) << 2;
            float4 v = *(const float4*)&X[(size_t)(row0 + r) * DM + k0 + j];
            *(uint4*)&As[r][j] = make_uint4(f2tf(v.x), f2tf(v.y), f2tf(v.z), f2tf(v.w));
        }
        #pragma unroll
        for (int i = 0; i < 4; i++) {
            int idx = tid + (i << 8);
            int k = idx >> 5, n = (idx & 31) << 2;
            int col = col0 + n;
            float4 v = *(const float4*)&W[((col >> 6) << 16) + ((k0 + k) << 6) + (col & 63)];
            *(uint4*)&Bs[k][n] = make_uint4(f2tf(v.x), f2tf(v.y), f2tf(v.z), f2tf(v.w));
        }
        __syncthreads();
        #pragma unroll
        for (int ks = 0; ks < 4; ks++) {
            const int kb = (ks << 3) + (lane & 3), rb = lane >> 2;
            unsigned a[4][4], bf[4][2];
            #pragma unroll
            for (int fm = 0; fm < 4; fm++) {
                int m = (wm << 6) + (fm << 4) + rb;
                a[fm][0] = As[m][kb];     a[fm][1] = As[m + 8][kb];
                a[fm][2] = As[m][kb + 4]; a[fm][3] = As[m + 8][kb + 4];
            }
            #pragma unroll
            for (int fn = 0; fn < 4; fn++) {
                int n = (wn << 5) + (fn << 3) + rb;
                bf[fn][0] = Bs[kb][n]; bf[fn][1] = Bs[kb + 4][n];
            }
            #pragma unroll
            for (int fm = 0; fm < 4; fm++)
                #pragma unroll
                for (int fn = 0; fn < 4; fn++)
                    mma_tf32(acc[fm][fn], a[fm], bf[fn]);
        }
        __syncthreads();
    }
    #pragma unroll
    for (int fn = 0; fn < 4; fn++) {
        int c = col0 + (wn << 5) + (fn << 3) + ((lane & 3) << 1);
        float b0 = bias[c], b1 = bias[c + 1];
        #pragma unroll
        for (int fm = 0; fm < 4; fm++) {
            int r = row0 + (wm << 6) + (fm << 4) + (lane >> 2);
            *(float2*)&out[(size_t)r * DM + c] =
                make_float2(acc[fm][fn][0] + b0, acc[fm][fn][1] + b1);
            *(float2*)&out[(size_t)(r + 8) * DM + c] =
                make_float2(acc[fm][fn][2] + b0, acc[fm][fn][3] + b1);
        }
    }
}

// ---------------------------------------------------------------------------
// Scores pass (computed ONCE): 128q x 128s tile per (b,h).
// tf32 QK^T, E = exp(score/8) -> fp16 to g_eh (smem-staged uint4 stores),
// deterministic per-qtile column partials -> g_part.
// ---------------------------------------------------------------------------
__global__ __launch_bounds__(256) void scores_mma()
{
    extern __shared__ __align__(16) unsigned dsm[];
    unsigned (*Qs)[68]  = (unsigned(*)[68])dsm;                 // [128][68] tf32 words
    unsigned (*Ksm)[68] = (unsigned(*)[68])(dsm + 128 * 68);    // [128][68]
    float (*red)[128]   = (float(*)[128])(dsm + 2 * 128 * 68);  // [16][128]
    __half* Estage = (__half*)dsm;                              // reuse Qs: [128][136] halves

    const int tid = threadIdx.x, lane = tid & 31, warp = tid >> 5;
    const int wm = warp >> 2, wn = warp & 3;
    const int z = blockIdx.z, b = z >> 4, h = z & 15;
    const int q0 = blockIdx.y << 7, s0 = blockIdx.x << 7;
    const float* qh = g_q + (size_t)b * 2048 * DM + h * 64;
    const float* kh = g_k + (size_t)b * 2048 * DM + h * 64;

    #pragma unroll
    for (int i = 0; i < 8; i++) {
        int idx = tid + (i << 8);
        int r = idx >> 4, j = (idx & 15) << 2;
        float4 v = *(const float4*)&qh[(size_t)(q0 + r) * DM + j];
        *(uint4*)&Qs[r][j] = make_uint4(f2tf(v.x), f2tf(v.y), f2tf(v.z), f2tf(v.w));
        float4 w = *(const float4*)&kh[(size_t)(s0 + r) * DM + j];
        *(uint4*)&Ksm[r][j] = make_uint4(f2tf(w.x), f2tf(w.y), f2tf(w.z), f2tf(w.w));
    }
    __syncthreads();

    float acc[4][4][4];
    #pragma unroll
    for (int i = 0; i < 4; i++)
        #pragma unroll
        for (int j = 0; j < 4; j++)
            #pragma unroll
            for (int k = 0; k < 4; k++) acc[i][j][k] = 0.f;

    #pragma unroll
    for (int ks = 0; ks < 8; ks++) {
        const int kb = (ks << 3) + (lane & 3), rb = lane >> 2;
        unsigned a[4][4], bf[4][2];
        #pragma unroll
        for (int fm = 0; fm < 4; fm++) {
            int m = (wm << 6) + (fm << 4) + rb;
            a[fm][0] = Qs[m][kb];     a[fm][1] = Qs[m + 8][kb];
            a[fm][2] = Qs[m][kb + 4]; a[fm][3] = Qs[m + 8][kb + 4];
        }
        #pragma unroll
        for (int fn = 0; fn < 4; fn++) {
            int n = (wn << 5) + (fn << 3) + rb;
            bf[fn][0] = Ksm[n][kb]; bf[fn][1] = Ksm[n][kb + 4];
        }
        #pragma unroll
        for (int fm = 0; fm < 4; fm++)
            #pragma unroll
            for (int fn = 0; fn < 4; fn++)
                mma_tf32(acc[fm][fn], a[fm], bf[fn]);
    }
    __syncthreads();   // all warps done reading Qs; safe to reuse as Estage

    float colacc[8];
    #pragma unroll
    for (int i = 0; i < 8; i++) colacc[i] = 0.f;
    const int rb = lane >> 2, c2 = (lane & 3) << 1;
    #pragma unroll
    for (int fm = 0; fm < 4; fm++) {
        int m0 = (wm << 6) + (fm << 4) + rb;
        #pragma unroll
        for (int fn = 0; fn < 4; fn++) {
            int n = (wn << 5) + (fn << 3) + c2;
            float e0 = __expf(acc[fm][fn][0] * 0.125f);
            float e1 = __expf(acc[fm][fn][1] * 0.125f);
            float e2 = __expf(acc[fm][fn][2] * 0.125f);
            float e3 = __expf(acc[fm][fn][3] * 0.125f);
            colacc[2 * fn]     += e0 + e2;
            colacc[2 * fn + 1] += e1 + e3;
            *(unsigned*)&Estage[m0 * 136 + n]       = packh2(e0, e1);
            *(unsigned*)&Estage[(m0 + 8) * 136 + n] = packh2(e2, e3);
        }
    }
    __syncthreads();

    __half* ez = g_eh + (size_t)z * 2048 * 2048;
    #pragma unroll
    for (int i = 0; i < 8; i++) {
        int idx = tid + (i << 8);
        int q = idx >> 4, w = idx & 15;
        *(uint4*)(ez + (size_t)(q0 + q) * 2048 + s0 + (w << 3)) =
            *(uint4*)&Estage[q * 136 + (w << 3)];
    }

    const int rg = (wm << 3) + rb;
    #pragma unroll
    for (int fn = 0; fn < 4; fn++) {
        int cc = (wn << 5) + (fn << 3) + c2;
        red[rg][cc]     = colacc[2 * fn];
        red[rg][cc + 1] = colacc[2 * fn + 1];
    }
    __syncthreads();
    if (tid < 128) {
        float s = 0.f;
        #pragma unroll
        for (int t = 0; t < 16; t++) s += red[t][tid];
        g_part[((size_t)z * 16 + blockIdx.y) * 2048 + s0 + tid] = s;
    }
}

// Reduce the 16 q-tile partials per column; 1/Z.
__global__ __launch_bounds__(256) void recip_kernel()
{
    int i = blockIdx.x * 256 + threadIdx.x;   // 64*2048
    int z = i >> 11, c = i & 2047;
    float s = 0.f;
    #pragma unroll
    for (int t = 0; t < 16; t++) s += g_part[((size_t)z * 16 + t) * 2048 + c];
    g_rz[i] = 1.0f / s;
}

// ---------------------------------------------------------------------------
// V' = V * rz  -> fp16 transposed: g_vt[z][dk][s]
// ---------------------------------------------------------------------------
__global__ __launch_bounds__(256) void v2h_fold()
{
    __shared__ float T[64][68];
    __shared__ float rzs[64];
    const int tid = threadIdx.x;
    const int z = blockIdx.y, b = z >> 4, h = z & 15;
    const int s0 = blockIdx.x << 6;
    const float* vh = g_v + (size_t)b * 2048 * DM + h * 64;
    #pragma unroll
    for (int i = 0; i < 4; i++) {
        int idx = tid + (i << 8);
        int s = idx >> 4, j = (idx & 15) << 2;
        *(float4*)&T[s][j] = *(const float4*)&vh[(size_t)(s0 + s) * DM + j];
    }
    if (tid < 64) rzs[tid] = g_rz[z * 2048 + s0 + tid];
    __syncthreads();
    __half* outp = g_vt + (size_t)z * 64 * 2048;
    #pragma unroll
    for (int i = 0; i < 4; i++) {
        int idx = tid + (i << 8);
        int dk = idx >> 4, sj = (idx & 15) << 2;
        uint2 u;
        u.x = packh2(T[sj][dk] * rzs[sj],         T[sj + 1][dk] * rzs[sj + 1]);
        u.y = packh2(T[sj + 2][dk] * rzs[sj + 2], T[sj + 3][dk] * rzs[sj + 3]);
        *(uint2*)(outp + dk * 2048 + s0 + sj) = u;
    }
}

// ---------------------------------------------------------------------------
// ctx = Eh @ V'^T per (b,h): [2048 x 64] = [2048 x 2048] x [2048 x 64].
// Pure fp16 mma, fp32 accum. Block: 128q x 64dk; 8 warps, each 16q x 64dk.
// cp.async double-buffered K-loop (64 s per stage, 32 stages).
// ---------------------------------------------------------------------------
#define CSTRIDE 88   // halves per row (64 + 24 pad): 176B rows (16B-aligned), conflict-free
__global__ __launch_bounds__(256, 2) void ctx_hgemm()
{
    extern __shared__ __align__(16) __half hsm[];
    const int STG = (128 + 64) * CSTRIDE;  // halves per stage

    const int tid = threadIdx.x, lane = tid & 31, warp = tid >> 5;
    const int z = blockIdx.y, b = z >> 4, h = z & 15;
    const int q0 = blockIdx.x << 7;
    const __half* ez = g_eh + (size_t)z * 2048 * 2048;
    const __half* vt = g_vt + (size_t)z * 64 * 2048;

    float acc[8][4];
    #pragma unroll
    for (int i = 0; i < 8; i++)
        #pragma unroll
        for (int j = 0; j < 4; j++) acc[i][j] = 0.f;

    auto load_stage = [&](int st, int s0) {
        __half* E = hsm + st * STG;
        __half* V = E + 128 * CSTRIDE;
        #pragma unroll
        for (int i = 0; i < 4; i++) {
            int idx = tid + (i << 8);
            int q = idx >> 3, w = idx & 7;
            cp16(E + q * CSTRIDE + (w << 3), ez + (size_t)(q0 + q) * 2048 + s0 + (w << 3));
        }
        #pragma unroll
        for (int i = 0; i < 2; i++) {
            int idx = tid + (i << 8);
            int dk = idx >> 3, w = idx & 7;
            cp16(V + dk * CSTRIDE + (w << 3), vt + dk * 2048 + s0 + (w << 3));
        }
        asm volatile("cp.async.commit_group;\n");
    };

    load_stage(0, 0);
    for (int it = 0; it < 32; it++) {
        const int st = it & 1;
        if (it + 1 < 32) {
            load_stage(st ^ 1, (it + 1) << 6);
            asm volatile("cp.async.wait_group 1;\n");
        } else {
            asm volatile("cp.async.wait_group 0;\n");
        }
        __syncthreads();
        const __half* E = hsm + st * STG;
        const __half* V = E + 128 * CSTRIDE;
        const int row = (warp << 4) + (lane >> 2);
        const int c2 = (lane & 3) << 1;
        #pragma unroll
        for (int kk = 0; kk < 4; kk++) {
            unsigned a[4];
            a[0] = *(const unsigned*)&E[row * CSTRIDE + (kk << 4) + c2];
            a[1] = *(const unsigned*)&E[(row + 8) * CSTRIDE + (kk << 4) + c2];
            a[2] = *(const unsigned*)&E[row * CSTRIDE + (kk << 4) + c2 + 8];
            a[3] = *(const unsigned*)&E[(row + 8) * CSTRIDE + (kk << 4) + c2 + 8];
            #pragma unroll
            for (int fb = 0; fb < 8; fb++) {
                int n = (fb << 3) + (lane >> 2);
                unsigned bb[2];
                bb[0] = *(const unsigned*)&V[n * CSTRIDE + (kk << 4) + c2];
                bb[1] = *(const unsigned*)&V[n * CSTRIDE + (kk << 4) + c2 + 8];
                mma_f16(acc[fb], a, bb);
            }
        }
        __syncthreads();
    }

    float* outp = g_ctx + ((size_t)b * 2048 + q0) * DM + h * 64;
    const int q = (warp << 4) + (lane >> 2);
    #pragma unroll
    for (int fb = 0; fb < 8; fb++) {
        int dk = (fb << 3) + ((lane & 3) << 1);
        *(float2*)&outp[(size_t)q * DM + dk]       = make_float2(acc[fb][0], acc[fb][1]);
        *(float2*)&outp[(size_t)(q + 8) * DM + dk] = make_float2(acc[fb][2], acc[fb][3]);
    }
}

// ---------------------------------------------------------------------------
// out = ctx @ Wo^T + bo
// ---------------------------------------------------------------------------
__global__ __launch_bounds__(256) void out_mma(const float* __restrict__ Wo,
                                               const float* __restrict__ bo,
                                               float* __restrict__ out)
{
    __shared__ __align__(16) unsigned As[128][36];   // [m][k]
    __shared__ __align__(16) unsigned Bs[128][36];   // [n][k]
    const int tid = threadIdx.x, lane = tid & 31, warp = tid >> 5;
    const int wm = warp >> 2, wn = warp & 3;
    const int row0 = blockIdx.y << 7, col0 = blockIdx.x << 7;

    float acc[4][4][4];
    #pragma unroll
    for (int i = 0; i < 4; i++)
        #pragma unroll
        for (int j = 0; j < 4; j++)
            #pragma unroll
            for (int k = 0; k < 4; k++) acc[i][j][k] = 0.f;

    for (int k0 = 0; k0 < DM; k0 += 32) {
        #pragma unroll
        for (int i = 0; i < 4; i++) {
            int idx = tid + (i << 8);
            int r = idx >> 3, j = (idx & 7) << 2;
            float4 v = *(const float4*)&g_ctx[(size_t)(row0 + r) * DM + k0 + j];
            *(uint4*)&As[r][j] = make_uint4(f2tf(v.x), f2tf(v.y), f2tf(v.z), f2tf(v.w));
        }
        #pragma unroll
        for (int i = 0; i < 4; i++) {
            int idx = tid + (i << 8);
            int n = idx >> 3, j = (idx & 7) << 2;
            float4 v = *(const float4*)&Wo[(size_t)(col0 + n) * DM + k0 + j];
            *(uint4*)&Bs[n][j] = make_uint4(f2tf(v.x), f2tf(v.y), f2tf(v.z), f2tf(v.w));
        }
        __syncthreads();
        #pragma unroll
        for (int ks = 0; ks < 4; ks++) {
            const int kb = (ks << 3) + (lane & 3), rb = lane >> 2;
            unsigned a[4][4], bf[4][2];
            #pragma unroll
            for (int fm = 0; fm < 4; fm++) {
                int m = (wm << 6) + (fm << 4) + rb;
                a[fm][0] = As[m][kb];     a[fm][1] = As[m + 8][kb];
                a[fm][2] = As[m][kb + 4]; a[fm][3] = As[m + 8][kb + 4];
            }
            #pragma unroll
            for (int fn = 0; fn < 4; fn++) {
                int n = (wn << 5) + (fn << 3) + rb;
                bf[fn][0] = Bs[n][kb]; bf[fn][1] = Bs[n][kb + 4];
            }
            #pragma unroll
            for (int fm = 0; fm < 4; fm++)
                #pragma unroll
                for (int fn = 0; fn < 4; fn++)
                    mma_tf32(acc[fm][fn], a[fm], bf[fn]);
        }
        __syncthreads();
    }
    #pragma unroll
    for (int fn = 0; fn < 4; fn++) {
        int c = col0 + (wn << 5) + (fn << 3) + ((lane & 3) << 1);
        float b0 = bo[c], b1 = bo[c + 1];
        #pragma unroll
        for (int fm = 0; fm < 4; fm++) {
            int r = row0 + (wm << 6) + (fm << 4) + (lane >> 2);
            *(float2*)&out[(size_t)r * DM + c] =
                make_float2(acc[fm][fn][0] + b0, acc[fm][fn][1] + b1);
            *(float2*)&out[(size_t)(r + 8) * DM + c] =
                make_float2(acc[fm][fn][2] + b0, acc[fm][fn][3] + b1);
        }
    }
}

extern "C" void kernel_launch(void* const* d_in, const int* in_sizes, int n_in,
                              void* d_out, int out_size)
{
    const float* query = (const float*)d_in[0];
    const float* key_  = (const float*)d_in[1];
    const float* value = (const float*)d_in[2];
    const float* Wq    = (const float*)d_in[3];
    const float* bq    = (const float*)d_in[4];
    const float* Wk    = (const float*)d_in[5];
    const float* bk    = (const float*)d_in[6];
    const float* Wv    = (const float*)d_in[7];
    const float* bv    = (const float*)d_in[8];
    const float* Wo    = (const float*)d_in[9];
    const float* bo    = (const float*)d_in[10];
    float* out = (float*)d_out;

    cudaFuncSetAttribute(scores_mma, cudaFuncAttributeMaxDynamicSharedMemorySize, 77824);
    cudaFuncSetAttribute(ctx_hgemm,  cudaFuncAttributeMaxDynamicSharedMemorySize,
                         2 * (128 + 64) * CSTRIDE * 2);

    proj_mma<<<dim3(8, 64, 3), 256>>>(query, key_, value, Wq, Wk, Wv, bq, bk, bv);
    scores_mma<<<dim3(16, 16, 64), 256, 77824>>>();
    recip_kernel<<<512, 256>>>();
    v2h_fold<<<dim3(32, 64), 256>>>();
    ctx_hgemm<<<dim3(16, 64), 256, 2 * (128 + 64) * CSTRIDE * 2>>>();
    out_mma<<<dim3(8, 64), 256>>>(Wo, bo, out);
}

// round 4
// speedup vs baseline: 4.9129x; 1.4521x over previous
#include <cuda_runtime.h>
#include <cuda_fp16.h>

#define DM 1024

// Scratch (device globals: allocation-free per harness rules)
__device__ __half g_xh[(size_t)3 * 8192 * 1024];   // fp16 query/key_/value
__device__ __half g_whq[1024 * 1024];              // per-head Wq as [n=h*64+dk][k=m]
__device__ __half g_whk[1024 * 1024];
__device__ __half g_whv[1024 * 1024];
__device__ __half g_woh[1024 * 1024];              // Wo [n][k] fp16
__device__ __half g_qh[(size_t)8192 * 1024];
__device__ __half g_kh[(size_t)8192 * 1024];
__device__ __half g_vh[(size_t)8192 * 1024];
__device__ __half g_eh[(size_t)64 * 2048 * 2048];  // E = exp(scores) fp16 (512 MiB)
__device__ float  g_part[64 * 16 * 2048];
__device__ float  g_rz[64 * 2048];
__device__ __half g_vt[(size_t)64 * 64 * 2048];    // V'^T fp16 [z][dk][s], 1/Z folded
__device__ __half g_ctxh[(size_t)8192 * 1024];

// ---------------------------------------------------------------------------
// helpers
// ---------------------------------------------------------------------------
__device__ __forceinline__ unsigned packh2(float lo, float hi) {
    unsigned r; asm("cvt.rn.f16x2.f32 %0, %1, %2;" : "=r"(r) : "f"(hi), "f"(lo)); return r;
}
__device__ __forceinline__ void mma_f16(float* c, const unsigned* a, const unsigned* b) {
    asm volatile("mma.sync.aligned.m16n8k16.row.col.f32.f16.f16.f32 "
        "{%0,%1,%2,%3},{%4,%5,%6,%7},{%8,%9},{%0,%1,%2,%3};"
        : "+f"(c[0]), "+f"(c[1]), "+f"(c[2]), "+f"(c[3])
        : "r"(a[0]), "r"(a[1]), "r"(a[2]), "r"(a[3]), "r"(b[0]), "r"(b[1]));
}
__device__ __forceinline__ void cp16(void* dst, const void* src) {
    unsigned d = (unsigned)__cvta_generic_to_shared(dst);
    asm volatile("cp.async.ca.shared.global [%0], [%1], 16;\n" :: "r"(d), "l"(src));
}

// ---------------------------------------------------------------------------
// Conversions
// ---------------------------------------------------------------------------
__global__ __launch_bounds__(256) void cvt_x(const float* __restrict__ q,
                                             const float* __restrict__ k,
                                             const float* __restrict__ v)
{
    const int z = blockIdx.z;
    const float* src = (z == 0) ? q : (z == 1) ? k : v;
    __half* dst = g_xh + (size_t)z * 8192 * 1024;
    size_t i = ((size_t)blockIdx.x * 256 + threadIdx.x) << 2;
    float4 val = *(const float4*)&src[i];
    uint2 u = make_uint2(packh2(val.x, val.y), packh2(val.z, val.w));
    *(uint2*)&dst[i] = u;
}

// W[h][m][dk] (stacked) -> Wh[n=h*64+dk][k=m] fp16, via 64x64 smem transpose.
__global__ __launch_bounds__(256) void cvt_w(const float* __restrict__ Wq,
                                             const float* __restrict__ Wk,
                                             const float* __restrict__ Wv)
{
    __shared__ float T[64][65];
    const int z = blockIdx.z;
    const float* W = (z == 0) ? Wq : (z == 1) ? Wk : Wv;
    __half* out = (z == 0) ? g_whq : (z == 1) ? g_whk : g_whv;
    const int h = blockIdx.y, k0 = blockIdx.x << 6;
    const int tid = threadIdx.x;
    #pragma unroll
    for (int i = 0; i < 4; i++) {
        int idx = tid + (i << 8);
        int kk = idx >> 4, j = (idx & 15) << 2;
        float4 v = *(const float4*)&W[(h << 16) + ((k0 + kk) << 6) + j];
        T[kk][j] = v.x; T[kk][j + 1] = v.y; T[kk][j + 2] = v.z; T[kk][j + 3] = v.w;
    }
    __syncthreads();
    #pragma unroll
    for (int i = 0; i < 4; i++) {
        int idx = tid + (i << 8);
        int dk = idx >> 4, kk = (idx & 15) << 2;
        uint2 u = make_uint2(packh2(T[kk][dk], T[kk + 1][dk]),
                             packh2(T[kk + 2][dk], T[kk + 3][dk]));
        *(uint2*)&out[(size_t)((h << 6) + dk) * 1024 + k0 + kk] = u;
    }
}

__global__ __launch_bounds__(256) void cvt_wo(const float* __restrict__ Wo)
{
    size_t i = ((size_t)blockIdx.x * 256 + threadIdx.x) << 2;
    float4 val = *(const float4*)&Wo[i];
    *(uint2*)&g_woh[i] = make_uint2(packh2(val.x, val.y), packh2(val.z, val.w));
}

// ---------------------------------------------------------------------------
// Generic fp16 GEMM body: C[128 x 128] tile, A[m][k], B[n][k], K=1024, BK=32,
// cp.async double-buffered. 8 warps (2x4), warp tile 64x32.
// ---------------------------------------------------------------------------
#define PSTRIDE 40   // halves per smem row (32 + 8 pad)

struct GemmAcc { float a[4][4][4]; };

__device__ __forceinline__ void hgemm_core(const __half* __restrict__ Ap,
                                           const __half* __restrict__ Bp,
                                           __half* sm, GemmAcc& g,
                                           int row0, int col0)
{
    const int tid = threadIdx.x, lane = tid & 31, warp = tid >> 5;
    const int wm = warp >> 2, wn = warp & 3;
    const int STG = 2 * 128 * PSTRIDE;   // halves per stage (A + B)

    #pragma unroll
    for (int i = 0; i < 4; i++)
        #pragma unroll
        for (int j = 0; j < 4; j++)
            #pragma unroll
            for (int k = 0; k < 4; k++) g.a[i][j][k] = 0.f;

    auto load_stage = [&](int st, int k0) {
        __half* A = sm + st * STG;
        __half* B = A + 128 * PSTRIDE;
        #pragma unroll
        for (int i = 0; i < 2; i++) {
            int idx = tid + (i << 8);
            int r = idx >> 2, w = (idx & 3) << 3;
            cp16(A + r * PSTRIDE + w, Ap + (size_t)(row0 + r) * 1024 + k0 + w);
        }
        #pragma unroll
        for (int i = 0; i < 2; i++) {
            int idx = tid + (i << 8);
            int n = idx >> 2, w = (idx & 3) << 3;
            cp16(B + n * PSTRIDE + w, Bp + (size_t)(col0 + n) * 1024 + k0 + w);
        }
        asm volatile("cp.async.commit_group;\n");
    };

    load_stage(0, 0);
    for (int it = 0; it < 32; it++) {
        const int st = it & 1;
        if (it + 1 < 32) {
            load_stage(st ^ 1, (it + 1) << 5);
            asm volatile("cp.async.wait_group 1;\n");
        } else {
            asm volatile("cp.async.wait_group 0;\n");
        }
        __syncthreads();
        const __half* A = sm + st * STG;
        const __half* B = A + 128 * PSTRIDE;
        const int rb = lane >> 2, c2 = (lane & 3) << 1;
        #pragma unroll
        for (int ks = 0; ks < 2; ks++) {
            const int kb = (ks << 4) + c2;
            unsigned a[4][4], bf[4][2];
            #pragma unroll
            for (int fm = 0; fm < 4; fm++) {
                int m = (wm << 6) + (fm << 4) + rb;
                a[fm][0] = *(const unsigned*)&A[m * PSTRIDE + kb];
                a[fm][1] = *(const unsigned*)&A[(m + 8) * PSTRIDE + kb];
                a[fm][2] = *(const unsigned*)&A[m * PSTRIDE + kb + 8];
                a[fm][3] = *(const unsigned*)&A[(m + 8) * PSTRIDE + kb + 8];
            }
            #pragma unroll
            for (int fn = 0; fn < 4; fn++) {
                int n = (wn << 5) + (fn << 3) + rb;
                bf[fn][0] = *(const unsigned*)&B[n * PSTRIDE + kb];
                bf[fn][1] = *(const unsigned*)&B[n * PSTRIDE + kb + 8];
            }
            #pragma unroll
            for (int fm = 0; fm < 4; fm++)
                #pragma unroll
                for (int fn = 0; fn < 4; fn++)
                    mma_f16(g.a[fm][fn], a[fm], bf[fn]);
        }
        __syncthreads();
    }
}

// Projections: q/k/v = Xh @ Wh^T + bias, output fp16.
__global__ __launch_bounds__(256, 2) void proj_hgemm(
    const float* __restrict__ bq, const float* __restrict__ bk, const float* __restrict__ bv)
{
    __shared__ __align__(16) __half sm[2 * 2 * 128 * PSTRIDE];
    const int zc = blockIdx.z;
    const __half* X  = g_xh + (size_t)zc * 8192 * 1024;
    const __half* Wh = (zc == 0) ? g_whq : (zc == 1) ? g_whk : g_whv;
    const float* bias = (zc == 0) ? bq : (zc == 1) ? bk : bv;
    __half* out = (zc == 0) ? g_qh : (zc == 1) ? g_kh : g_vh;

    const int row0 = blockIdx.y << 7, col0 = blockIdx.x << 7;
    GemmAcc g;
    hgemm_core(X, Wh, sm, g, row0, col0);

    const int lane = threadIdx.x & 31, warp = threadIdx.x >> 5;
    const int wm = warp >> 2, wn = warp & 3;
    const int rb = lane >> 2, c2 = (lane & 3) << 1;
    #pragma unroll
    for (int fn = 0; fn < 4; fn++) {
        int c = col0 + (wn << 5) + (fn << 3) + c2;
        float b0 = bias[c], b1 = bias[c + 1];
        #pragma unroll
        for (int fm = 0; fm < 4; fm++) {
            int r = row0 + (wm << 6) + (fm << 4) + rb;
            *(unsigned*)&out[(size_t)r * 1024 + c] = packh2(g.a[fm][fn][0] + b0, g.a[fm][fn][1] + b1);
            *(unsigned*)&out[(size_t)(r + 8) * 1024 + c] = packh2(g.a[fm][fn][2] + b0, g.a[fm][fn][3] + b1);
        }
    }
}

// Output projection: out = ctx @ Wo^T + bo, fp32 output.
__global__ __launch_bounds__(256, 2) void out_hgemm(const float* __restrict__ bo,
                                                    float* __restrict__ out)
{
    __shared__ __align__(16) __half sm[2 * 2 * 128 * PSTRIDE];
    const int row0 = blockIdx.y << 7, col0 = blockIdx.x << 7;
    GemmAcc g;
    hgemm_core(g_ctxh, g_woh, sm, g, row0, col0);

    const int lane = threadIdx.x & 31, warp = threadIdx.x >> 5;
    const int wm = warp >> 2, wn = warp & 3;
    const int rb = lane >> 2, c2 = (lane & 3) << 1;
    #pragma unroll
    for (int fn = 0; fn < 4; fn++) {
        int c = col0 + (wn << 5) + (fn << 3) + c2;
        float b0 = bo[c], b1 = bo[c + 1];
        #pragma unroll
        for (int fm = 0; fm < 4; fm++) {
            int r = row0 + (wm << 6) + (fm << 4) + rb;
            *(float2*)&out[(size_t)r * 1024 + c] =
                make_float2(g.a[fm][fn][0] + b0, g.a[fm][fn][1] + b1);
            *(float2*)&out[(size_t)(r + 8) * 1024 + c] =
                make_float2(g.a[fm][fn][2] + b0, g.a[fm][fn][3] + b1);
        }
    }
}

// ---------------------------------------------------------------------------
// Scores pass (once): 128q x 128s tile per (b,h), fp16 QK^T (K=64),
// E = exp(score/8) -> fp16 to g_eh (staged uint4 stores), column partials.
// ---------------------------------------------------------------------------
#define SSTRIDE 72
__global__ __launch_bounds__(256) void scores_hmma()
{
    __shared__ __align__(16) __half qk[2 * 128 * SSTRIDE];  // Qs then Ks
    __shared__ float red[16][128];
    __half* Qs = qk;
    __half* Ks = qk + 128 * SSTRIDE;
    __half* Estage = qk;   // reused after mma: [128][136]

    const int tid = threadIdx.x, lane = tid & 31, warp = tid >> 5;
    const int wm = warp >> 2, wn = warp & 3;
    const int z = blockIdx.z, b = z >> 4, h = z & 15;
    const int q0 = blockIdx.y << 7, s0 = blockIdx.x << 7;
    const __half* qh = g_qh + (size_t)b * 2048 * 1024 + h * 64;
    const __half* kh = g_kh + (size_t)b * 2048 * 1024 + h * 64;

    #pragma unroll
    for (int i = 0; i < 4; i++) {
        int idx = tid + (i << 8);
        int r = idx >> 3, w = (idx & 7) << 3;
        *(uint4*)&Qs[r * SSTRIDE + w] = *(const uint4*)&qh[(size_t)(q0 + r) * 1024 + w];
        *(uint4*)&Ks[r * SSTRIDE + w] = *(const uint4*)&kh[(size_t)(s0 + r) * 1024 + w];
    }
    __syncthreads();

    float acc[4][4][4];
    #pragma unroll
    for (int i = 0; i < 4; i++)
        #pragma unroll
        for (int j = 0; j < 4; j++)
            #pragma unroll
            for (int k = 0; k < 4; k++) acc[i][j][k] = 0.f;

    const int rb = lane >> 2, c2 = (lane & 3) << 1;
    #pragma unroll
    for (int ks = 0; ks < 4; ks++) {
        const int kb = (ks << 4) + c2;
        unsigned a[4][4], bf[4][2];
        #pragma unroll
        for (int fm = 0; fm < 4; fm++) {
            int m = (wm << 6) + (fm << 4) + rb;
            a[fm][0] = *(const unsigned*)&Qs[m * SSTRIDE + kb];
            a[fm][1] = *(const unsigned*)&Qs[(m + 8) * SSTRIDE + kb];
            a[fm][2] = *(const unsigned*)&Qs[m * SSTRIDE + kb + 8];
            a[fm][3] = *(const unsigned*)&Qs[(m + 8) * SSTRIDE + kb + 8];
        }
        #pragma unroll
        for (int fn = 0; fn < 4; fn++) {
            int n = (wn << 5) + (fn << 3) + rb;
            bf[fn][0] = *(const unsigned*)&Ks[n * SSTRIDE + kb];
            bf[fn][1] = *(const unsigned*)&Ks[n * SSTRIDE + kb + 8];
        }
        #pragma unroll
        for (int fm = 0; fm < 4; fm++)
            #pragma unroll
            for (int fn = 0; fn < 4; fn++)
                mma_f16(acc[fm][fn], a[fm], bf[fn]);
    }
    __syncthreads();   // done reading Qs/Ks; safe to reuse as Estage

    float colacc[8];
    #pragma unroll
    for (int i = 0; i < 8; i++) colacc[i] = 0.f;
    #pragma unroll
    for (int fm = 0; fm < 4; fm++) {
        int m0 = (wm << 6) + (fm << 4) + rb;
        #pragma unroll
        for (int fn = 0; fn < 4; fn++) {
            int n = (wn << 5) + (fn << 3) + c2;
            float e0 = __expf(acc[fm][fn][0] * 0.125f);
            float e1 = __expf(acc[fm][fn][1] * 0.125f);
            float e2 = __expf(acc[fm][fn][2] * 0.125f);
            float e3 = __expf(acc[fm][fn][3] * 0.125f);
            colacc[2 * fn]     += e0 + e2;
            colacc[2 * fn + 1] += e1 + e3;
            *(unsigned*)&Estage[m0 * 136 + n]       = packh2(e0, e1);
            *(unsigned*)&Estage[(m0 + 8) * 136 + n] = packh2(e2, e3);
        }
    }
    __syncthreads();

    __half* ez = g_eh + (size_t)z * 2048 * 2048;
    #pragma unroll
    for (int i = 0; i < 8; i++) {
        int idx = tid + (i << 8);
        int q = idx >> 4, w = idx & 15;
        *(uint4*)(ez + (size_t)(q0 + q) * 2048 + s0 + (w << 3)) =
            *(uint4*)&Estage[q * 136 + (w << 3)];
    }

    const int rg = (wm << 3) + rb;
    #pragma unroll
    for (int fn = 0; fn < 4; fn++) {
        int cc = (wn << 5) + (fn << 3) + c2;
        red[rg][cc]     = colacc[2 * fn];
        red[rg][cc + 1] = colacc[2 * fn + 1];
    }
    __syncthreads();
    if (tid < 128) {
        float s = 0.f;
        #pragma unroll
        for (int t = 0; t < 16; t++) s += red[t][tid];
        g_part[((size_t)z * 16 + blockIdx.y) * 2048 + s0 + tid] = s;
    }
}

// Reduce the 16 q-tile partials per column; 1/Z.
__global__ __launch_bounds__(256) void recip_kernel()
{
    int i = blockIdx.x * 256 + threadIdx.x;   // 64*2048
    int z = i >> 11, c = i & 2047;
    float s = 0.f;
    #pragma unroll
    for (int t = 0; t < 16; t++) s += g_part[((size_t)z * 16 + t) * 2048 + c];
    g_rz[i] = 1.0f / s;
}

// ---------------------------------------------------------------------------
// V' = V * rz -> fp16 transposed: g_vt[z][dk][s]
// ---------------------------------------------------------------------------
__global__ __launch_bounds__(256) void v2h_fold()
{
    __shared__ float T[64][68];
    __shared__ float rzs[64];
    const int tid = threadIdx.x;
    const int z = blockIdx.y, b = z >> 4, h = z & 15;
    const int s0 = blockIdx.x << 6;
    const __half* vh = g_vh + (size_t)b * 2048 * 1024 + h * 64;
    #pragma unroll
    for (int i = 0; i < 4; i++) {
        int idx = tid + (i << 8);
        int s = idx >> 4, j = (idx & 15) << 2;
        const __half* p = vh + (size_t)(s0 + s) * 1024 + j;
        T[s][j]     = __half2float(p[0]);
        T[s][j + 1] = __half2float(p[1]);
        T[s][j + 2] = __half2float(p[2]);
        T[s][j + 3] = __half2float(p[3]);
    }
    if (tid < 64) rzs[tid] = g_rz[z * 2048 + s0 + tid];
    __syncthreads();
    __half* outp = g_vt + (size_t)z * 64 * 2048;
    #pragma unroll
    for (int i = 0; i < 4; i++) {
        int idx = tid + (i << 8);
        int dk = idx >> 4, sj = (idx & 15) << 2;
        uint2 u;
        u.x = packh2(T[sj][dk] * rzs[sj],         T[sj + 1][dk] * rzs[sj + 1]);
        u.y = packh2(T[sj + 2][dk] * rzs[sj + 2], T[sj + 3][dk] * rzs[sj + 3]);
        *(uint2*)(outp + dk * 2048 + s0 + sj) = u;
    }
}

// ---------------------------------------------------------------------------
// ctx = Eh @ V'^T per (b,h): [2048 x 64] = [2048 x 2048] x [2048 x 64].
// fp16 mma, fp32 accum, cp.async double-buffered; fp16 ctx output.
// ---------------------------------------------------------------------------
#define CSTRIDE 88
__global__ __launch_bounds__(256, 2) void ctx_hgemm()
{
    extern __shared__ __align__(16) __half hsm[];
    const int STG = (128 + 64) * CSTRIDE;

    const int tid = threadIdx.x, lane = tid & 31, warp = tid >> 5;
    const int z = blockIdx.y, b = z >> 4, h = z & 15;
    const int q0 = blockIdx.x << 7;
    const __half* ez = g_eh + (size_t)z * 2048 * 2048;
    const __half* vt = g_vt + (size_t)z * 64 * 2048;

    float acc[8][4];
    #pragma unroll
    for (int i = 0; i < 8; i++)
        #pragma unroll
        for (int j = 0; j < 4; j++) acc[i][j] = 0.f;

    auto load_stage = [&](int st, int s0) {
        __half* E = hsm + st * STG;
        __half* V = E + 128 * CSTRIDE;
        #pragma unroll
        for (int i = 0; i < 4; i++) {
            int idx = tid + (i << 8);
            int q = idx >> 3, w = idx & 7;
            cp16(E + q * CSTRIDE + (w << 3), ez + (size_t)(q0 + q) * 2048 + s0 + (w << 3));
        }
        #pragma unroll
        for (int i = 0; i < 2; i++) {
            int idx = tid + (i << 8);
            int dk = idx >> 3, w = idx & 7;
            cp16(V + dk * CSTRIDE + (w << 3), vt + dk * 2048 + s0 + (w << 3));
        }
        asm volatile("cp.async.commit_group;\n");
    };

    load_stage(0, 0);
    for (int it = 0; it < 32; it++) {
        const int st = it & 1;
        if (it + 1 < 32) {
            load_stage(st ^ 1, (it + 1) << 6);
            asm volatile("cp.async.wait_group 1;\n");
        } else {
            asm volatile("cp.async.wait_group 0;\n");
        }
        __syncthreads();
        const __half* E = hsm + st * STG;
        const __half* V = E + 128 * CSTRIDE;
        const int row = (warp << 4) + (lane >> 2);
        const int c2 = (lane & 3) << 1;
        #pragma unroll
        for (int kk = 0; kk < 4; kk++) {
            unsigned a[4];
            a[0] = *(const unsigned*)&E[row * CSTRIDE + (kk << 4) + c2];
            a[1] = *(const unsigned*)&E[(row + 8) * CSTRIDE + (kk << 4) + c2];
            a[2] = *(const unsigned*)&E[row * CSTRIDE + (kk << 4) + c2 + 8];
            a[3] = *(const unsigned*)&E[(row + 8) * CSTRIDE + (kk << 4) + c2 + 8];
            #pragma unroll
            for (int fb = 0; fb < 8; fb++) {
                int n = (fb << 3) + (lane >> 2);
                unsigned bb[2];
                bb[0] = *(const unsigned*)&V[n * CSTRIDE + (kk << 4) + c2];
                bb[1] = *(const unsigned*)&V[n * CSTRIDE + (kk << 4) + c2 + 8];
                mma_f16(acc[fb], a, bb);
            }
        }
        __syncthreads();
    }

    __half* outp = g_ctxh + ((size_t)b * 2048 + q0) * 1024 + h * 64;
    const int q = (warp << 4) + (lane >> 2);
    const int c2 = (lane & 3) << 1;
    #pragma unroll
    for (int fb = 0; fb < 8; fb++) {
        int dk = (fb << 3) + c2;
        *(unsigned*)&outp[(size_t)q * 1024 + dk]       = packh2(acc[fb][0], acc[fb][1]);
        *(unsigned*)&outp[(size_t)(q + 8) * 1024 + dk] = packh2(acc[fb][2], acc[fb][3]);
    }
}

extern "C" void kernel_launch(void* const* d_in, const int* in_sizes, int n_in,
                              void* d_out, int out_size)
{
    const float* query = (const float*)d_in[0];
    const float* key_  = (const float*)d_in[1];
    const float* value = (const float*)d_in[2];
    const float* Wq    = (const float*)d_in[3];
    const float* bq    = (const float*)d_in[4];
    const float* Wk    = (const float*)d_in[5];
    const float* bk    = (const float*)d_in[6];
    const float* Wv    = (const float*)d_in[7];
    const float* bv    = (const float*)d_in[8];
    const float* Wo    = (const float*)d_in[9];
    const float* bo    = (const float*)d_in[10];
    float* out = (float*)d_out;

    cudaFuncSetAttribute(ctx_hgemm, cudaFuncAttributeMaxDynamicSharedMemorySize,
                         2 * (128 + 64) * CSTRIDE * 2);

    cvt_x<<<dim3(8192, 1, 3), 256>>>(query, key_, value);
    cvt_w<<<dim3(16, 16, 3), 256>>>(Wq, Wk, Wv);
    cvt_wo<<<1024, 256>>>(Wo);
    proj_hgemm<<<dim3(8, 64, 3), 256>>>(bq, bk, bv);
    scores_hmma<<<dim3(16, 16, 64), 256>>>();
    recip_kernel<<<512, 256>>>();
    v2h_fold<<<dim3(32, 64), 256>>>();
    ctx_hgemm<<<dim3(16, 64), 256, 2 * (128 + 64) * CSTRIDE * 2>>>();
    out_hgemm<<<dim3(8, 64), 256>>>(bo, out);
}

// round 7
// speedup vs baseline: 5.1590x; 1.0501x over previous
#include <cuda_runtime.h>
#include <cuda_fp16.h>
#include <cstdint>

#define DM 1024

// Scratch (device globals: allocation-free per harness rules)
__device__ __half g_xh[(size_t)3 * 8192 * 1024];   // fp16 query/key_/value
__device__ __half g_whq[1024 * 1024];              // per-head Wq as [n=h*64+dk][k=m]
__device__ __half g_whk[1024 * 1024];
__device__ __half g_whv[1024 * 1024];
__device__ __half g_woh[1024 * 1024];              // Wo [n][k] fp16
__device__ __half g_qh[(size_t)8192 * 1024];
__device__ __half g_kh[(size_t)8192 * 1024];
__device__ __half g_vh[(size_t)8192 * 1024];
__device__ __half g_eh[(size_t)64 * 2048 * 2048];  // E = exp(scores) fp16 (512 MiB)
__device__ float  g_part[64 * 16 * 2048];
__device__ float  g_rz[64 * 2048];
__device__ __half g_vt[(size_t)64 * 64 * 2048];    // V'^T fp16 [z][dk][s], 1/Z folded
__device__ __half g_ctxh[(size_t)8192 * 1024];

// ---------------------------------------------------------------------------
// helpers
// ---------------------------------------------------------------------------
__device__ __forceinline__ unsigned packh2(float lo, float hi) {
    unsigned r; asm("cvt.rn.f16x2.f32 %0, %1, %2;" : "=r"(r) : "f"(hi), "f"(lo)); return r;
}
__device__ __forceinline__ void mma_f16(float* c, const unsigned* a, const unsigned* b) {
    asm volatile("mma.sync.aligned.m16n8k16.row.col.f32.f16.f16.f32 "
        "{%0,%1,%2,%3},{%4,%5,%6,%7},{%8,%9},{%0,%1,%2,%3};"
        : "+f"(c[0]), "+f"(c[1]), "+f"(c[2]), "+f"(c[3])
        : "r"(a[0]), "r"(a[1]), "r"(a[2]), "r"(a[3]), "r"(b[0]), "r"(b[1]));
}
__device__ __forceinline__ void cp16(void* dst, const void* src) {
    unsigned d = (unsigned)__cvta_generic_to_shared(dst);
    asm volatile("cp.async.ca.shared.global [%0], [%1], 16;\n" :: "r"(d), "l"(src));
}
#define LDMX4(r0, r1, r2, r3, addr) \
    asm volatile("ldmatrix.sync.aligned.m8n8.x4.shared.b16 {%0,%1,%2,%3}, [%4];" \
        : "=r"(r0), "=r"(r1), "=r"(r2), "=r"(r3) : "r"(addr))
__device__ __forceinline__ uint32_t s2u(const void* p) {
    return (uint32_t)__cvta_generic_to_shared(p);
}

// ---------------------------------------------------------------------------
// Conversions
// ---------------------------------------------------------------------------
__global__ __launch_bounds__(256) void cvt_x(const float* __restrict__ q,
                                             const float* __restrict__ k,
                                             const float* __restrict__ v)
{
    const int z = blockIdx.z;
    const float* src = (z == 0) ? q : (z == 1) ? k : v;
    __half* dst = g_xh + (size_t)z * 8192 * 1024;
    size_t i = ((size_t)blockIdx.x * 256 + threadIdx.x) << 2;
    float4 val = *(const float4*)&src[i];
    *(uint2*)&dst[i] = make_uint2(packh2(val.x, val.y), packh2(val.z, val.w));
}

__global__ __launch_bounds__(256) void cvt_w(const float* __restrict__ Wq,
                                             const float* __restrict__ Wk,
                                             const float* __restrict__ Wv)
{
    __shared__ float T[64][65];
    const int z = blockIdx.z;
    const float* W = (z == 0) ? Wq : (z == 1) ? Wk : Wv;
    __half* out = (z == 0) ? g_whq : (z == 1) ? g_whk : g_whv;
    const int h = blockIdx.y, k0 = blockIdx.x << 6;
    const int tid = threadIdx.x;
    #pragma unroll
    for (int i = 0; i < 4; i++) {
        int idx = tid + (i << 8);
        int kk = idx >> 4, j = (idx & 15) << 2;
        float4 v = *(const float4*)&W[(h << 16) + ((k0 + kk) << 6) + j];
        T[kk][j] = v.x; T[kk][j + 1] = v.y; T[kk][j + 2] = v.z; T[kk][j + 3] = v.w;
    }
    __syncthreads();
    #pragma unroll
    for (int i = 0; i < 4; i++) {
        int idx = tid + (i << 8);
        int dk = idx >> 4, kk = (idx & 15) << 2;
        uint2 u = make_uint2(packh2(T[kk][dk], T[kk + 1][dk]),
                             packh2(T[kk + 2][dk], T[kk + 3][dk]));
        *(uint2*)&out[(size_t)((h << 6) + dk) * 1024 + k0 + kk] = u;
    }
}

__global__ __launch_bounds__(256) void cvt_wo(const float* __restrict__ Wo)
{
    size_t i = ((size_t)blockIdx.x * 256 + threadIdx.x) << 2;
    float4 val = *(const float4*)&Wo[i];
    *(uint2*)&g_woh[i] = make_uint2(packh2(val.x, val.y), packh2(val.z, val.w));
}

// ---------------------------------------------------------------------------
// Generic fp16 GEMM body: C[128 x 128] tile, A[m][k], B[n][k], K=1024, BK=32,
// cp.async double-buffered, ldmatrix fragment loads. 8 warps, warp tile 64x32.
// ---------------------------------------------------------------------------
#define PSTRIDE 40   // halves per smem row (32 + 8 pad); rows 80B apart

struct GemmAcc { float a[4][4][4]; };

__device__ __forceinline__ void hgemm_core(const __half* __restrict__ Ap,
                                           const __half* __restrict__ Bp,
                                           __half* sm, GemmAcc& g,
                                           int row0, int col0)
{
    const int tid = threadIdx.x, lane = tid & 31, warp = tid >> 5;
    const int wm = warp >> 2, wn = warp & 3;
    const int STG = 2 * 128 * PSTRIDE;   // halves per stage (A + B)

    #pragma unroll
    for (int i = 0; i < 4; i++)
        #pragma unroll
        for (int j = 0; j < 4; j++)
            #pragma unroll
            for (int k = 0; k < 4; k++) g.a[i][j][k] = 0.f;

    // per-thread ldmatrix address components (bytes)
    const uint32_t arow_off = (uint32_t)(((lane & 15) * PSTRIDE + ((lane >> 4) << 3)) << 1);
    const uint32_t brow_off = (uint32_t)(((((lane & 16) >> 1) + (lane & 7)) * PSTRIDE + (lane & 8)) << 1);

    auto load_stage = [&](int st, int k0) {
        __half* A = sm + st * STG;
        __half* B = A + 128 * PSTRIDE;
        #pragma unroll
        for (int i = 0; i < 2; i++) {
            int idx = tid + (i << 8);
            int r = idx >> 2, w = (idx & 3) << 3;
            cp16(A + r * PSTRIDE + w, Ap + (size_t)(row0 + r) * 1024 + k0 + w);
        }
        #pragma unroll
        for (int i = 0; i < 2; i++) {
            int idx = tid + (i << 8);
            int n = idx >> 2, w = (idx & 3) << 3;
            cp16(B + n * PSTRIDE + w, Bp + (size_t)(col0 + n) * 1024 + k0 + w);
        }
        asm volatile("cp.async.commit_group;\n");
    };

    load_stage(0, 0);
    for (int it = 0; it < 32; it++) {
        const int st = it & 1;
        if (it + 1 < 32) {
            load_stage(st ^ 1, (it + 1) << 5);
            asm volatile("cp.async.wait_group 1;\n");
        } else {
            asm volatile("cp.async.wait_group 0;\n");
        }
        __syncthreads();
        const uint32_t Au = s2u(sm + st * STG);
        const uint32_t Bu = Au + (uint32_t)(128 * PSTRIDE * 2);
        #pragma unroll
        for (int ks = 0; ks < 2; ks++) {
            const int kb0 = ks << 4;
            unsigned a[4][4], bf[4][2];
            #pragma unroll
            for (int fm = 0; fm < 4; fm++) {
                uint32_t addr = Au + arow_off +
                    (uint32_t)(((((wm << 6) + (fm << 4)) * PSTRIDE + kb0)) << 1);
                LDMX4(a[fm][0], a[fm][1], a[fm][2], a[fm][3], addr);
            }
            #pragma unroll
            for (int p = 0; p < 2; p++) {
                uint32_t addr = Bu + brow_off +
                    (uint32_t)(((((wn << 5) + (p << 4)) * PSTRIDE + kb0)) << 1);
                LDMX4(bf[2 * p][0], bf[2 * p][1], bf[2 * p + 1][0], bf[2 * p + 1][1], addr);
            }
            #pragma unroll
            for (int fm = 0; fm < 4; fm++)
                #pragma unroll
                for (int fn = 0; fn < 4; fn++)
                    mma_f16(g.a[fm][fn], a[fm], bf[fn]);
        }
        __syncthreads();
    }
}

// Projections: q/k/v = Xh @ Wh^T + bias, output fp16.
__global__ __launch_bounds__(256, 2) void proj_hgemm(
    const float* __restrict__ bq, const float* __restrict__ bk, const float* __restrict__ bv)
{
    __shared__ __align__(16) __half sm[2 * 2 * 128 * PSTRIDE];
    const int zc = blockIdx.z;
    const __half* X  = g_xh + (size_t)zc * 8192 * 1024;
    const __half* Wh = (zc == 0) ? g_whq : (zc == 1) ? g_whk : g_whv;
    const float* bias = (zc == 0) ? bq : (zc == 1) ? bk : bv;
    __half* out = (zc == 0) ? g_qh : (zc == 1) ? g_kh : g_vh;

    const int row0 = blockIdx.y << 7, col0 = blockIdx.x << 7;
    GemmAcc g;
    hgemm_core(X, Wh, sm, g, row0, col0);

    const int lane = threadIdx.x & 31, warp = threadIdx.x >> 5;
    const int wm = warp >> 2, wn = warp & 3;
    const int rb = lane >> 2, c2 = (lane & 3) << 1;
    #pragma unroll
    for (int fn = 0; fn < 4; fn++) {
        int c = col0 + (wn << 5) + (fn << 3) + c2;
        float b0 = bias[c], b1 = bias[c + 1];
        #pragma unroll
        for (int fm = 0; fm < 4; fm++) {
            int r = row0 + (wm << 6) + (fm << 4) + rb;
            *(unsigned*)&out[(size_t)r * 1024 + c] = packh2(g.a[fm][fn][0] + b0, g.a[fm][fn][1] + b1);
            *(unsigned*)&out[(size_t)(r + 8) * 1024 + c] = packh2(g.a[fm][fn][2] + b0, g.a[fm][fn][3] + b1);
        }
    }
}

// Output projection: out = ctx @ Wo^T + bo, fp32 output.
__global__ __launch_bounds__(256, 2) void out_hgemm(const float* __restrict__ bo,
                                                    float* __restrict__ out)
{
    __shared__ __align__(16) __half sm[2 * 2 * 128 * PSTRIDE];
    const int row0 = blockIdx.y << 7, col0 = blockIdx.x << 7;
    GemmAcc g;
    hgemm_core(g_ctxh, g_woh, sm, g, row0, col0);

    const int lane = threadIdx.x & 31, warp = threadIdx.x >> 5;
    const int wm = warp >> 2, wn = warp & 3;
    const int rb = lane >> 2, c2 = (lane & 3) << 1;
    #pragma unroll
    for (int fn = 0; fn < 4; fn++) {
        int c = col0 + (wn << 5) + (fn << 3) + c2;
        float b0 = bo[c], b1 = bo[c + 1];
        #pragma unroll
        for (int fm = 0; fm < 4; fm++) {
            int r = row0 + (wm << 6) + (fm << 4) + rb;
            *(float2*)&out[(size_t)r * 1024 + c] =
                make_float2(g.a[fm][fn][0] + b0, g.a[fm][fn][1] + b1);
            *(float2*)&out[(size_t)(r + 8) * 1024 + c] =
                make_float2(g.a[fm][fn][2] + b0, g.a[fm][fn][3] + b1);
        }
    }
}

// ---------------------------------------------------------------------------
// Scores pass (once): 128q x 128s tile per (b,h), fp16 QK^T (K=64),
// E = exp(score/8) -> fp16 to g_eh (staged uint4 stores), column partials.
// ldmatrix fragment loads.
// ---------------------------------------------------------------------------
#define SSTRIDE 72
__global__ __launch_bounds__(256) void scores_hmma()
{
    __shared__ __align__(16) __half qk[2 * 128 * SSTRIDE];
    __shared__ float red[16][128];
    __half* Qs = qk;
    __half* Ks = qk + 128 * SSTRIDE;
    __half* Estage = qk;   // reused after mma: [128][136]

    const int tid = threadIdx.x, lane = tid & 31, warp = tid >> 5;
    const int wm = warp >> 2, wn = warp & 3;
    const int z = blockIdx.z, b = z >> 4, h = z & 15;
    const int q0 = blockIdx.y << 7, s0 = blockIdx.x << 7;
    const __half* qh = g_qh + (size_t)b * 2048 * 1024 + h * 64;
    const __half* kh = g_kh + (size_t)b * 2048 * 1024 + h * 64;

    #pragma unroll
    for (int i = 0; i < 4; i++) {
        int idx = tid + (i << 8);
        int r = idx >> 3, w = (idx & 7) << 3;
        *(uint4*)&Qs[r * SSTRIDE + w] = *(const uint4*)&qh[(size_t)(q0 + r) * 1024 + w];
        *(uint4*)&Ks[r * SSTRIDE + w] = *(const uint4*)&kh[(size_t)(s0 + r) * 1024 + w];
    }
    __syncthreads();

    float acc[4][4][4];
    #pragma unroll
    for (int i = 0; i < 4; i++)
        #pragma unroll
        for (int j = 0; j < 4; j++)
            #pragma unroll
            for (int k = 0; k < 4; k++) acc[i][j][k] = 0.f;

    const uint32_t Qu = s2u(Qs), Ku = s2u(Ks);
    const uint32_t arow_off = (uint32_t)(((lane & 15) * SSTRIDE + ((lane >> 4) << 3)) << 1);
    const uint32_t brow_off = (uint32_t)(((((lane & 16) >> 1) + (lane & 7)) * SSTRIDE + (lane & 8)) << 1);
    const int rb = lane >> 2, c2 = (lane & 3) << 1;

    #pragma unroll
    for (int ks = 0; ks < 4; ks++) {
        const int kb0 = ks << 4;
        unsigned a[4][4], bf[4][2];
        #pragma unroll
        for (int fm = 0; fm < 4; fm++) {
            uint32_t addr = Qu + arow_off +
                (uint32_t)((((wm << 6) + (fm << 4)) * SSTRIDE + kb0) << 1);
            LDMX4(a[fm][0], a[fm][1], a[fm][2], a[fm][3], addr);
        }
        #pragma unroll
        for (int p = 0; p < 2; p++) {
            uint32_t addr = Ku + brow_off +
                (uint32_t)((((wn << 5) + (p << 4)) * SSTRIDE + kb0) << 1);
            LDMX4(bf[2 * p][0], bf[2 * p][1], bf[2 * p + 1][0], bf[2 * p + 1][1], addr);
        }
        #pragma unroll
        for (int fm = 0; fm < 4; fm++)
            #pragma unroll
            for (int fn = 0; fn < 4; fn++)
                mma_f16(acc[fm][fn], a[fm], bf[fn]);
    }
    __syncthreads();

    float colacc[8];
    #pragma unroll
    for (int i = 0; i < 8; i++) colacc[i] = 0.f;
    #pragma unroll
    for (int fm = 0; fm < 4; fm++) {
        int m0 = (wm << 6) + (fm << 4) + rb;
        #pragma unroll
        for (int fn = 0; fn < 4; fn++) {
            int n = (wn << 5) + (fn << 3) + c2;
            float e0 = __expf(acc[fm][fn][0] * 0.125f);
            float e1 = __expf(acc[fm][fn][1] * 0.125f);
            float e2 = __expf(acc[fm][fn][2] * 0.125f);
            float e3 = __expf(acc[fm][fn][3] * 0.125f);
            colacc[2 * fn]     += e0 + e2;
            colacc[2 * fn + 1] += e1 + e3;
            *(unsigned*)&Estage[m0 * 136 + n]       = packh2(e0, e1);
            *(unsigned*)&Estage[(m0 + 8) * 136 + n] = packh2(e2, e3);
        }
    }
    __syncthreads();

    __half* ez = g_eh + (size_t)z * 2048 * 2048;
    #pragma unroll
    for (int i = 0; i < 8; i++) {
        int idx = tid + (i << 8);
        int q = idx >> 4, w = idx & 15;
        *(uint4*)(ez + (size_t)(q0 + q) * 2048 + s0 + (w << 3)) =
            *(uint4*)&Estage[q * 136 + (w << 3)];
    }

    const int rg = (wm << 3) + rb;
    #pragma unroll
    for (int fn = 0; fn < 4; fn++) {
        int cc = (wn << 5) + (fn << 3) + c2;
        red[rg][cc]     = colacc[2 * fn];
        red[rg][cc + 1] = colacc[2 * fn + 1];
    }
    __syncthreads();
    if (tid < 128) {
        float s = 0.f;
        #pragma unroll
        for (int t = 0; t < 16; t++) s += red[t][tid];
        g_part[((size_t)z * 16 + blockIdx.y) * 2048 + s0 + tid] = s;
    }
}

// Reduce the 16 q-tile partials per column; 1/Z.
__global__ __launch_bounds__(256) void recip_kernel()
{
    int i = blockIdx.x * 256 + threadIdx.x;
    int z = i >> 11, c = i & 2047;
    float s = 0.f;
    #pragma unroll
    for (int t = 0; t < 16; t++) s += g_part[((size_t)z * 16 + t) * 2048 + c];
    g_rz[i] = 1.0f / s;
}

// ---------------------------------------------------------------------------
// V' = V * rz -> fp16 transposed: g_vt[z][dk][s]
// ---------------------------------------------------------------------------
__global__ __launch_bounds__(256) void v2h_fold()
{
    __shared__ float T[64][68];
    __shared__ float rzs[64];
    const int tid = threadIdx.x;
    const int z = blockIdx.y, b = z >> 4, h = z & 15;
    const int s0 = blockIdx.x << 6;
    const __half* vh = g_vh + (size_t)b * 2048 * 1024 + h * 64;
    #pragma unroll
    for (int i = 0; i < 4; i++) {
        int idx = tid + (i << 8);
        int s = idx >> 4, j = (idx & 15) << 2;
        const __half* p = vh + (size_t)(s0 + s) * 1024 + j;
        T[s][j]     = __half2float(p[0]);
        T[s][j + 1] = __half2float(p[1]);
        T[s][j + 2] = __half2float(p[2]);
        T[s][j + 3] = __half2float(p[3]);
    }
    if (tid < 64) rzs[tid] = g_rz[z * 2048 + s0 + tid];
    __syncthreads();
    __half* outp = g_vt + (size_t)z * 64 * 2048;
    #pragma unroll
    for (int i = 0; i < 4; i++) {
        int idx = tid + (i << 8);
        int dk = idx >> 4, sj = (idx & 15) << 2;
        uint2 u;
        u.x = packh2(T[sj][dk] * rzs[sj],         T[sj + 1][dk] * rzs[sj + 1]);
        u.y = packh2(T[sj + 2][dk] * rzs[sj + 2], T[sj + 3][dk] * rzs[sj + 3]);
        *(uint2*)(outp + dk * 2048 + s0 + sj) = u;
    }
}

// ---------------------------------------------------------------------------
// ctx = Eh @ V'^T per (b,h): [2048 x 64] = [2048 x 2048] x [2048 x 64].
// fp16 mma, fp32 accum, cp.async double-buffered, ldmatrix loads; fp16 out.
// ---------------------------------------------------------------------------
#define CSTRIDE 88
__global__ __launch_bounds__(256, 2) void ctx_hgemm()
{
    extern __shared__ __align__(16) __half hsm[];
    const int STG = (128 + 64) * CSTRIDE;

    const int tid = threadIdx.x, lane = tid & 31, warp = tid >> 5;
    const int z = blockIdx.y, b = z >> 4, h = z & 15;
    const int q0 = blockIdx.x << 7;
    const __half* ez = g_eh + (size_t)z * 2048 * 2048;
    const __half* vt = g_vt + (size_t)z * 64 * 2048;

    float acc[8][4];
    #pragma unroll
    for (int i = 0; i < 8; i++)
        #pragma unroll
        for (int j = 0; j < 4; j++) acc[i][j] = 0.f;

    const uint32_t arow_off = (uint32_t)(((lane & 15) * CSTRIDE + ((lane >> 4) << 3)) << 1);
    const uint32_t brow_off = (uint32_t)(((((lane & 16) >> 1) + (lane & 7)) * CSTRIDE + (lane & 8)) << 1);

    auto load_stage = [&](int st, int s0) {
        __half* E = hsm + st * STG;
        __half* V = E + 128 * CSTRIDE;
        #pragma unroll
        for (int i = 0; i < 4; i++) {
            int idx = tid + (i << 8);
            int q = idx >> 3, w = idx & 7;
            cp16(E + q * CSTRIDE + (w << 3), ez + (size_t)(q0 + q) * 2048 + s0 + (w << 3));
        }
        #pragma unroll
        for (int i = 0; i < 2; i++) {
            int idx = tid + (i << 8);
            int dk = idx >> 3, w = idx & 7;
            cp16(V + dk * CSTRIDE + (w << 3), vt + dk * 2048 + s0 + (w << 3));
        }
        asm volatile("cp.async.commit_group;\n");
    };

    load_stage(0, 0);
    for (int it = 0; it < 32; it++) {
        const int st = it & 1;
        if (it + 1 < 32) {
            load_stage(st ^ 1, (it + 1) << 6);
            asm volatile("cp.async.wait_group 1;\n");
        } else {
            asm volatile("cp.async.wait_group 0;\n");
        }
        __syncthreads();
        const uint32_t Eu = s2u(hsm + st * STG);
        const uint32_t Vu = Eu + (uint32_t)(128 * CSTRIDE * 2);
        const int m = warp << 4;
        #pragma unroll
        for (int kk = 0; kk < 4; kk++) {
            const int kb0 = kk << 4;
            unsigned a[4];
            LDMX4(a[0], a[1], a[2], a[3],
                  Eu + arow_off + (uint32_t)((m * CSTRIDE + kb0) << 1));
            unsigned bf[8][2];
            #pragma unroll
            for (int p = 0; p < 4; p++) {
                LDMX4(bf[2 * p][0], bf[2 * p][1], bf[2 * p + 1][0], bf[2 * p + 1][1],
                      Vu + brow_off + (uint32_t)(((p << 4) * CSTRIDE + kb0) << 1));
            }
            #pragma unroll
            for (int fb = 0; fb < 8; fb++)
                mma_f16(acc[fb], a, bf[fb]);
        }
        __syncthreads();
    }

    __half* outp = g_ctxh + ((size_t)b * 2048 + q0) * 1024 + h * 64;
    const int q = (warp << 4) + (lane >> 2);
    const int c2 = (lane & 3) << 1;
    #pragma unroll
    for (int fb = 0; fb < 8; fb++) {
        int dk = (fb << 3) + c2;
        *(unsigned*)&outp[(size_t)q * 1024 + dk]       = packh2(acc[fb][0], acc[fb][1]);
        *(unsigned*)&outp[(size_t)(q + 8) * 1024 + dk] = packh2(acc[fb][2], acc[fb][3]);
    }
}

extern "C" void kernel_launch(void* const* d_in, const int* in_sizes, int n_in,
                              void* d_out, int out_size)
{
    const float* query = (const float*)d_in[0];
    const float* key_  = (const float*)d_in[1];
    const float* value = (const float*)d_in[2];
    const float* Wq    = (const float*)d_in[3];
    const float* bq    = (const float*)d_in[4];
    const float* Wk    = (const float*)d_in[5];
    const float* bk    = (const float*)d_in[6];
    const float* Wv    = (const float*)d_in[7];
    const float* bv    = (const float*)d_in[8];
    const float* Wo    = (const float*)d_in[9];
    const float* bo    = (const float*)d_in[10];
    float* out = (float*)d_out;

    cudaFuncSetAttribute(ctx_hgemm, cudaFuncAttributeMaxDynamicSharedMemorySize,
                         2 * (128 + 64) * CSTRIDE * 2);

    cvt_x<<<dim3(8192, 1, 3), 256>>>(query, key_, value);
    cvt_w<<<dim3(16, 16, 3), 256>>>(Wq, Wk, Wv);
    cvt_wo<<<1024, 256>>>(Wo);
    proj_hgemm<<<dim3(8, 64, 3), 256>>>(bq, bk, bv);
    scores_hmma<<<dim3(16, 16, 64), 256>>>();
    recip_kernel<<<512, 256>>>();
    v2h_fold<<<dim3(32, 64), 256>>>();
    ctx_hgemm<<<dim3(16, 64), 256, 2 * (128 + 64) * CSTRIDE * 2>>>();
    out_hgemm<<<dim3(8, 64), 256>>>(bo, out);
}

// round 8
// speedup vs baseline: 5.6369x; 1.0926x over previous
#include <cuda_runtime.h>
#include <cuda_fp16.h>
#include <cstdint>

#define DM 1024

// Scratch (device globals: allocation-free per harness rules)
__device__ __half g_xh[(size_t)3 * 8192 * 1024];   // fp16 query/key_/value
__device__ __half g_whq[1024 * 1024];              // per-head Wq as [n=h*64+dk][k=m]
__device__ __half g_whk[1024 * 1024];
__device__ __half g_whv[1024 * 1024];
__device__ __half g_woh[1024 * 1024];              // Wo [n][k] fp16
__device__ __half g_qh[(size_t)8192 * 1024];
__device__ __half g_kh[(size_t)8192 * 1024];
__device__ __half g_vh[(size_t)8192 * 1024];
__device__ __half g_eh[(size_t)64 * 2048 * 2048];  // E = exp(scores) fp16 (512 MiB)
__device__ float  g_part[64 * 16 * 2048];
__device__ float  g_rz[64 * 2048];
__device__ __half g_vt[(size_t)64 * 64 * 2048];    // V'^T fp16 [z][dk][s], 1/Z folded
__device__ __half g_ctxh[(size_t)8192 * 1024];

// ---------------------------------------------------------------------------
// helpers
// ---------------------------------------------------------------------------
__device__ __forceinline__ unsigned packh2(float lo, float hi) {
    unsigned r; asm("cvt.rn.f16x2.f32 %0, %1, %2;" : "=r"(r) : "f"(hi), "f"(lo)); return r;
}
__device__ __forceinline__ void mma_f16(float* c, const unsigned* a, const unsigned* b) {
    asm volatile("mma.sync.aligned.m16n8k16.row.col.f32.f16.f16.f32 "
        "{%0,%1,%2,%3},{%4,%5,%6,%7},{%8,%9},{%0,%1,%2,%3};"
        : "+f"(c[0]), "+f"(c[1]), "+f"(c[2]), "+f"(c[3])
        : "r"(a[0]), "r"(a[1]), "r"(a[2]), "r"(a[3]), "r"(b[0]), "r"(b[1]));
}
__device__ __forceinline__ void cp16(void* dst, const void* src) {
    unsigned d = (unsigned)__cvta_generic_to_shared(dst);
    asm volatile("cp.async.ca.shared.global [%0], [%1], 16;\n" :: "r"(d), "l"(src));
}
#define LDMX4(r0, r1, r2, r3, addr) \
    asm volatile("ldmatrix.sync.aligned.m8n8.x4.shared.b16 {%0,%1,%2,%3}, [%4];" \
        : "=r"(r0), "=r"(r1), "=r"(r2), "=r"(r3) : "r"(addr))
__device__ __forceinline__ uint32_t s2u(const void* p) {
    return (uint32_t)__cvta_generic_to_shared(p);
}

// ---------------------------------------------------------------------------
// Conversions
// ---------------------------------------------------------------------------
__global__ __launch_bounds__(256) void cvt_x(const float* __restrict__ q,
                                             const float* __restrict__ k,
                                             const float* __restrict__ v)
{
    const int z = blockIdx.z;
    const float* src = (z == 0) ? q : (z == 1) ? k : v;
    __half* dst = g_xh + (size_t)z * 8192 * 1024;
    size_t i = ((size_t)blockIdx.x * 256 + threadIdx.x) << 2;
    float4 val = *(const float4*)&src[i];
    *(uint2*)&dst[i] = make_uint2(packh2(val.x, val.y), packh2(val.z, val.w));
}

__global__ __launch_bounds__(256) void cvt_w(const float* __restrict__ Wq,
                                             const float* __restrict__ Wk,
                                             const float* __restrict__ Wv)
{
    __shared__ float T[64][65];
    const int z = blockIdx.z;
    const float* W = (z == 0) ? Wq : (z == 1) ? Wk : Wv;
    __half* out = (z == 0) ? g_whq : (z == 1) ? g_whk : g_whv;
    const int h = blockIdx.y, k0 = blockIdx.x << 6;
    const int tid = threadIdx.x;
    #pragma unroll
    for (int i = 0; i < 4; i++) {
        int idx = tid + (i << 8);
        int kk = idx >> 4, j = (idx & 15) << 2;
        float4 v = *(const float4*)&W[(h << 16) + ((k0 + kk) << 6) + j];
        T[kk][j] = v.x; T[kk][j + 1] = v.y; T[kk][j + 2] = v.z; T[kk][j + 3] = v.w;
    }
    __syncthreads();
    #pragma unroll
    for (int i = 0; i < 4; i++) {
        int idx = tid + (i << 8);
        int dk = idx >> 4, kk = (idx & 15) << 2;
        uint2 u = make_uint2(packh2(T[kk][dk], T[kk + 1][dk]),
                             packh2(T[kk + 2][dk], T[kk + 3][dk]));
        *(uint2*)&out[(size_t)((h << 6) + dk) * 1024 + k0 + kk] = u;
    }
}

__global__ __launch_bounds__(256) void cvt_wo(const float* __restrict__ Wo)
{
    size_t i = ((size_t)blockIdx.x * 256 + threadIdx.x) << 2;
    float4 val = *(const float4*)&Wo[i];
    *(uint2*)&g_woh[i] = make_uint2(packh2(val.x, val.y), packh2(val.z, val.w));
}

// ---------------------------------------------------------------------------
// Generic fp16 GEMM body: C[128 x 128] tile, A[m][k], B[n][k], K=1024, BK=64,
// cp.async double-buffered, ldmatrix fragment loads. 8 warps, warp tile 64x32.
// ---------------------------------------------------------------------------
#define PSTRIDE 72   // halves per smem row (64 + 8 pad); rows 144B apart

struct GemmAcc { float a[4][4][4]; };

__device__ __forceinline__ void hgemm_core(const __half* __restrict__ Ap,
                                           const __half* __restrict__ Bp,
                                           __half* sm, GemmAcc& g,
                                           int row0, int col0)
{
    const int tid = threadIdx.x, lane = tid & 31, warp = tid >> 5;
    const int wm = warp >> 2, wn = warp & 3;
    const int STG = 2 * 128 * PSTRIDE;   // halves per stage (A + B)

    #pragma unroll
    for (int i = 0; i < 4; i++)
        #pragma unroll
        for (int j = 0; j < 4; j++)
            #pragma unroll
            for (int k = 0; k < 4; k++) g.a[i][j][k] = 0.f;

    // per-thread ldmatrix address components (bytes)
    const uint32_t arow_off = (uint32_t)(((lane & 15) * PSTRIDE + ((lane >> 4) << 3)) << 1);
    const uint32_t brow_off = (uint32_t)(((((lane & 16) >> 1) + (lane & 7)) * PSTRIDE + (lane & 8)) << 1);

    auto load_stage = [&](int st, int k0) {
        __half* A = sm + st * STG;
        __half* B = A + 128 * PSTRIDE;
        #pragma unroll
        for (int i = 0; i < 4; i++) {
            int idx = tid + (i << 8);
            int r = idx >> 3, w = (idx & 7) << 3;
            cp16(A + r * PSTRIDE + w, Ap + (size_t)(row0 + r) * 1024 + k0 + w);
        }
        #pragma unroll
        for (int i = 0; i < 4; i++) {
            int idx = tid + (i << 8);
            int n = idx >> 3, w = (idx & 7) << 3;
            cp16(B + n * PSTRIDE + w, Bp + (size_t)(col0 + n) * 1024 + k0 + w);
        }
        asm volatile("cp.async.commit_group;\n");
    };

    load_stage(0, 0);
    for (int it = 0; it < 16; it++) {
        const int st = it & 1;
        if (it + 1 < 16) {
            load_stage(st ^ 1, (it + 1) << 6);
            asm volatile("cp.async.wait_group 1;\n");
        } else {
            asm volatile("cp.async.wait_group 0;\n");
        }
        __syncthreads();
        const uint32_t Au = s2u(sm + st * STG);
        const uint32_t Bu = Au + (uint32_t)(128 * PSTRIDE * 2);
        #pragma unroll
        for (int ks = 0; ks < 4; ks++) {
            const int kb0 = ks << 4;
            unsigned a[4][4], bf[4][2];
            #pragma unroll
            for (int fm = 0; fm < 4; fm++) {
                uint32_t addr = Au + arow_off +
                    (uint32_t)(((((wm << 6) + (fm << 4)) * PSTRIDE + kb0)) << 1);
                LDMX4(a[fm][0], a[fm][1], a[fm][2], a[fm][3], addr);
            }
            #pragma unroll
            for (int p = 0; p < 2; p++) {
                uint32_t addr = Bu + brow_off +
                    (uint32_t)(((((wn << 5) + (p << 4)) * PSTRIDE + kb0)) << 1);
                LDMX4(bf[2 * p][0], bf[2 * p][1], bf[2 * p + 1][0], bf[2 * p + 1][1], addr);
            }
            #pragma unroll
            for (int fm = 0; fm < 4; fm++)
                #pragma unroll
                for (int fn = 0; fn < 4; fn++)
                    mma_f16(g.a[fm][fn], a[fm], bf[fn]);
        }
        __syncthreads();
    }
}

#define PROJ_SMEM (2 * 2 * 128 * PSTRIDE * 2)   // bytes: 2 stages x (A+B)

// Projections: q/k/v = Xh @ Wh^T + bias, output fp16.
__global__ __launch_bounds__(256, 2) void proj_hgemm(
    const float* __restrict__ bq, const float* __restrict__ bk, const float* __restrict__ bv)
{
    extern __shared__ __align__(16) __half psm[];
    const int zc = blockIdx.z;
    const __half* X  = g_xh + (size_t)zc * 8192 * 1024;
    const __half* Wh = (zc == 0) ? g_whq : (zc == 1) ? g_whk : g_whv;
    const float* bias = (zc == 0) ? bq : (zc == 1) ? bk : bv;
    __half* out = (zc == 0) ? g_qh : (zc == 1) ? g_kh : g_vh;

    const int row0 = blockIdx.y << 7, col0 = blockIdx.x << 7;
    GemmAcc g;
    hgemm_core(X, Wh, psm, g, row0, col0);

    const int lane = threadIdx.x & 31, warp = threadIdx.x >> 5;
    const int wm = warp >> 2, wn = warp & 3;
    const int rb = lane >> 2, c2 = (lane & 3) << 1;
    #pragma unroll
    for (int fn = 0; fn < 4; fn++) {
        int c = col0 + (wn << 5) + (fn << 3) + c2;
        float b0 = bias[c], b1 = bias[c + 1];
        #pragma unroll
        for (int fm = 0; fm < 4; fm++) {
            int r = row0 + (wm << 6) + (fm << 4) + rb;
            *(unsigned*)&out[(size_t)r * 1024 + c] = packh2(g.a[fm][fn][0] + b0, g.a[fm][fn][1] + b1);
            *(unsigned*)&out[(size_t)(r + 8) * 1024 + c] = packh2(g.a[fm][fn][2] + b0, g.a[fm][fn][3] + b1);
        }
    }
}

// Output projection: out = ctx @ Wo^T + bo, fp32 output.
__global__ __launch_bounds__(256, 2) void out_hgemm(const float* __restrict__ bo,
                                                    float* __restrict__ out)
{
    extern __shared__ __align__(16) __half psm[];
    const int row0 = blockIdx.y << 7, col0 = blockIdx.x << 7;
    GemmAcc g;
    hgemm_core(g_ctxh, g_woh, psm, g, row0, col0);

    const int lane = threadIdx.x & 31, warp = threadIdx.x >> 5;
    const int wm = warp >> 2, wn = warp & 3;
    const int rb = lane >> 2, c2 = (lane & 3) << 1;
    #pragma unroll
    for (int fn = 0; fn < 4; fn++) {
        int c = col0 + (wn << 5) + (fn << 3) + c2;
        float b0 = bo[c], b1 = bo[c + 1];
        #pragma unroll
        for (int fm = 0; fm < 4; fm++) {
            int r = row0 + (wm << 6) + (fm << 4) + rb;
            *(float2*)&out[(size_t)r * 1024 + c] =
                make_float2(g.a[fm][fn][0] + b0, g.a[fm][fn][1] + b1);
            *(float2*)&out[(size_t)(r + 8) * 1024 + c] =
                make_float2(g.a[fm][fn][2] + b0, g.a[fm][fn][3] + b1);
        }
    }
}

// ---------------------------------------------------------------------------
// Scores pass (once): 128q x 128s tile per (b,h), fp16 QK^T (K=64),
// E = exp(score/8) -> fp16 to g_eh (staged uint4 stores), column partials.
// (validated round-7 path, unchanged)
// ---------------------------------------------------------------------------
#define SSTRIDE 72
__global__ __launch_bounds__(256) void scores_hmma()
{
    __shared__ __align__(16) __half qk[2 * 128 * SSTRIDE];
    __shared__ float red[16][128];
    __half* Qs = qk;
    __half* Ks = qk + 128 * SSTRIDE;
    __half* Estage = qk;   // reused after mma: [128][136]

    const int tid = threadIdx.x, lane = tid & 31, warp = tid >> 5;
    const int wm = warp >> 2, wn = warp & 3;
    const int z = blockIdx.z, b = z >> 4, h = z & 15;
    const int q0 = blockIdx.y << 7, s0 = blockIdx.x << 7;
    const __half* qh = g_qh + (size_t)b * 2048 * 1024 + h * 64;
    const __half* kh = g_kh + (size_t)b * 2048 * 1024 + h * 64;

    #pragma unroll
    for (int i = 0; i < 4; i++) {
        int idx = tid + (i << 8);
        int r = idx >> 3, w = (idx & 7) << 3;
        *(uint4*)&Qs[r * SSTRIDE + w] = *(const uint4*)&qh[(size_t)(q0 + r) * 1024 + w];
        *(uint4*)&Ks[r * SSTRIDE + w] = *(const uint4*)&kh[(size_t)(s0 + r) * 1024 + w];
    }
    __syncthreads();

    float acc[4][4][4];
    #pragma unroll
    for (int i = 0; i < 4; i++)
        #pragma unroll
        for (int j = 0; j < 4; j++)
            #pragma unroll
            for (int k = 0; k < 4; k++) acc[i][j][k] = 0.f;

    const uint32_t Qu = s2u(Qs), Ku = s2u(Ks);
    const uint32_t arow_off = (uint32_t)(((lane & 15) * SSTRIDE + ((lane >> 4) << 3)) << 1);
    const uint32_t brow_off = (uint32_t)(((((lane & 16) >> 1) + (lane & 7)) * SSTRIDE + (lane & 8)) << 1);
    const int rb = lane >> 2, c2 = (lane & 3) << 1;

    #pragma unroll
    for (int ks = 0; ks < 4; ks++) {
        const int kb0 = ks << 4;
        unsigned a[4][4], bf[4][2];
        #pragma unroll
        for (int fm = 0; fm < 4; fm++) {
            uint32_t addr = Qu + arow_off +
                (uint32_t)((((wm << 6) + (fm << 4)) * SSTRIDE + kb0) << 1);
            LDMX4(a[fm][0], a[fm][1], a[fm][2], a[fm][3], addr);
        }
        #pragma unroll
        for (int p = 0; p < 2; p++) {
            uint32_t addr = Ku + brow_off +
                (uint32_t)((((wn << 5) + (p << 4)) * SSTRIDE + kb0) << 1);
            LDMX4(bf[2 * p][0], bf[2 * p][1], bf[2 * p + 1][0], bf[2 * p + 1][1], addr);
        }
        #pragma unroll
        for (int fm = 0; fm < 4; fm++)
            #pragma unroll
            for (int fn = 0; fn < 4; fn++)
                mma_f16(acc[fm][fn], a[fm], bf[fn]);
    }
    __syncthreads();

    float colacc[8];
    #pragma unroll
    for (int i = 0; i < 8; i++) colacc[i] = 0.f;
    #pragma unroll
    for (int fm = 0; fm < 4; fm++) {
        int m0 = (wm << 6) + (fm << 4) + rb;
        #pragma unroll
        for (int fn = 0; fn < 4; fn++) {
            int n = (wn << 5) + (fn << 3) + c2;
            float e0 = __expf(acc[fm][fn][0] * 0.125f);
            float e1 = __expf(acc[fm][fn][1] * 0.125f);
            float e2 = __expf(acc[fm][fn][2] * 0.125f);
            float e3 = __expf(acc[fm][fn][3] * 0.125f);
            colacc[2 * fn]     += e0 + e2;
            colacc[2 * fn + 1] += e1 + e3;
            *(unsigned*)&Estage[m0 * 136 + n]       = packh2(e0, e1);
            *(unsigned*)&Estage[(m0 + 8) * 136 + n] = packh2(e2, e3);
        }
    }
    __syncthreads();

    __half* ez = g_eh + (size_t)z * 2048 * 2048;
    #pragma unroll
    for (int i = 0; i < 8; i++) {
        int idx = tid + (i << 8);
        int q = idx >> 4, w = idx & 15;
        *(uint4*)(ez + (size_t)(q0 + q) * 2048 + s0 + (w << 3)) =
            *(uint4*)&Estage[q * 136 + (w << 3)];
    }

    const int rg = (wm << 3) + rb;
    #pragma unroll
    for (int fn = 0; fn < 4; fn++) {
        int cc = (wn << 5) + (fn << 3) + c2;
        red[rg][cc]     = colacc[2 * fn];
        red[rg][cc + 1] = colacc[2 * fn + 1];
    }
    __syncthreads();
    if (tid < 128) {
        float s = 0.f;
        #pragma unroll
        for (int t = 0; t < 16; t++) s += red[t][tid];
        g_part[((size_t)z * 16 + blockIdx.y) * 2048 + s0 + tid] = s;
    }
}

// Reduce the 16 q-tile partials per column; 1/Z.
__global__ __launch_bounds__(256) void recip_kernel()
{
    int i = blockIdx.x * 256 + threadIdx.x;
    int z = i >> 11, c = i & 2047;
    float s = 0.f;
    #pragma unroll
    for (int t = 0; t < 16; t++) s += g_part[((size_t)z * 16 + t) * 2048 + c];
    g_rz[i] = 1.0f / s;
}

// ---------------------------------------------------------------------------
// V' = V * rz -> fp16 transposed: g_vt[z][dk][s]
// ---------------------------------------------------------------------------
__global__ __launch_bounds__(256) void v2h_fold()
{
    __shared__ float T[64][68];
    __shared__ float rzs[64];
    const int tid = threadIdx.x;
    const int z = blockIdx.y, b = z >> 4, h = z & 15;
    const int s0 = blockIdx.x << 6;
    const __half* vh = g_vh + (size_t)b * 2048 * 1024 + h * 64;
    #pragma unroll
    for (int i = 0; i < 4; i++) {
        int idx = tid + (i << 8);
        int s = idx >> 4, j = (idx & 15) << 2;
        const __half* p = vh + (size_t)(s0 + s) * 1024 + j;
        T[s][j]     = __half2float(p[0]);
        T[s][j + 1] = __half2float(p[1]);
        T[s][j + 2] = __half2float(p[2]);
        T[s][j + 3] = __half2float(p[3]);
    }
    if (tid < 64) rzs[tid] = g_rz[z * 2048 + s0 + tid];
    __syncthreads();
    __half* outp = g_vt + (size_t)z * 64 * 2048;
    #pragma unroll
    for (int i = 0; i < 4; i++) {
        int idx = tid + (i << 8);
        int dk = idx >> 4, sj = (idx & 15) << 2;
        uint2 u;
        u.x = packh2(T[sj][dk] * rzs[sj],         T[sj + 1][dk] * rzs[sj + 1]);
        u.y = packh2(T[sj + 2][dk] * rzs[sj + 2], T[sj + 3][dk] * rzs[sj + 3]);
        *(uint2*)(outp + dk * 2048 + s0 + sj) = u;
    }
}

// ---------------------------------------------------------------------------
// ctx = Eh @ V'^T per (b,h): [2048 x 64] = [2048 x 2048] x [2048 x 64].
// Block 256q x 64dk; 8 warps, each 32q x 64dk (B frags serve 2x the HMMA).
// fp16 mma, fp32 accum, cp.async double-buffered, ldmatrix loads; fp16 out.
// ---------------------------------------------------------------------------
#define CSTRIDE 72
__global__ __launch_bounds__(256, 2) void ctx_hgemm()
{
    extern __shared__ __align__(16) __half hsm[];
    const int STG = (256 + 64) * CSTRIDE;   // halves per stage (E 256 rows + V 64 rows)

    const int tid = threadIdx.x, lane = tid & 31, warp = tid >> 5;
    const int z = blockIdx.y, b = z >> 4, h = z & 15;
    const int q0 = blockIdx.x << 8;
    const __half* ez = g_eh + (size_t)z * 2048 * 2048;
    const __half* vt = g_vt + (size_t)z * 64 * 2048;

    float acc[2][8][4];
    #pragma unroll
    for (int f = 0; f < 2; f++)
        #pragma unroll
        for (int i = 0; i < 8; i++)
            #pragma unroll
            for (int j = 0; j < 4; j++) acc[f][i][j] = 0.f;

    const uint32_t arow_off = (uint32_t)(((lane & 15) * CSTRIDE + ((lane >> 4) << 3)) << 1);
    const uint32_t brow_off = (uint32_t)(((((lane & 16) >> 1) + (lane & 7)) * CSTRIDE + (lane & 8)) << 1);

    auto load_stage = [&](int st, int s0) {
        __half* E = hsm + st * STG;
        __half* V = E + 256 * CSTRIDE;
        #pragma unroll
        for (int i = 0; i < 8; i++) {
            int idx = tid + (i << 8);
            int q = idx >> 3, w = idx & 7;
            cp16(E + q * CSTRIDE + (w << 3), ez + (size_t)(q0 + q) * 2048 + s0 + (w << 3));
        }
        #pragma unroll
        for (int i = 0; i < 2; i++) {
            int idx = tid + (i << 8);
            int dk = idx >> 3, w = idx & 7;
            cp16(V + dk * CSTRIDE + (w << 3), vt + dk * 2048 + s0 + (w << 3));
        }
        asm volatile("cp.async.commit_group;\n");
    };

    load_stage(0, 0);
    for (int it = 0; it < 32; it++) {
        const int st = it & 1;
        if (it + 1 < 32) {
            load_stage(st ^ 1, (it + 1) << 6);
            asm volatile("cp.async.wait_group 1;\n");
        } else {
            asm volatile("cp.async.wait_group 0;\n");
        }
        __syncthreads();
        const uint32_t Eu = s2u(hsm + st * STG);
        const uint32_t Vu = Eu + (uint32_t)(256 * CSTRIDE * 2);
        const int m0 = warp << 5;
        #pragma unroll
        for (int kk = 0; kk < 4; kk++) {
            const int kb0 = kk << 4;
            unsigned a[2][4];
            #pragma unroll
            for (int fm = 0; fm < 2; fm++)
                LDMX4(a[fm][0], a[fm][1], a[fm][2], a[fm][3],
                      Eu + arow_off + (uint32_t)(((m0 + (fm << 4)) * CSTRIDE + kb0) << 1));
            unsigned bf[8][2];
            #pragma unroll
            for (int p = 0; p < 4; p++) {
                LDMX4(bf[2 * p][0], bf[2 * p][1], bf[2 * p + 1][0], bf[2 * p + 1][1],
                      Vu + brow_off + (uint32_t)(((p << 4) * CSTRIDE + kb0) << 1));
            }
            #pragma unroll
            for (int fm = 0; fm < 2; fm++)
                #pragma unroll
                for (int fb = 0; fb < 8; fb++)
                    mma_f16(acc[fm][fb], a[fm], bf[fb]);
        }
        __syncthreads();
    }

    __half* outp = g_ctxh + ((size_t)b * 2048 + q0) * 1024 + h * 64;
    const int c2 = (lane & 3) << 1;
    #pragma unroll
    for (int fm = 0; fm < 2; fm++) {
        const int q = (warp << 5) + (fm << 4) + (lane >> 2);
        #pragma unroll
        for (int fb = 0; fb < 8; fb++) {
            int dk = (fb << 3) + c2;
            *(unsigned*)&outp[(size_t)q * 1024 + dk]       = packh2(acc[fm][fb][0], acc[fm][fb][1]);
            *(unsigned*)&outp[(size_t)(q + 8) * 1024 + dk] = packh2(acc[fm][fb][2], acc[fm][fb][3]);
        }
    }
}

extern "C" void kernel_launch(void* const* d_in, const int* in_sizes, int n_in,
                              void* d_out, int out_size)
{
    const float* query = (const float*)d_in[0];
    const float* key_  = (const float*)d_in[1];
    const float* value = (const float*)d_in[2];
    const float* Wq    = (const float*)d_in[3];
    const float* bq    = (const float*)d_in[4];
    const float* Wk    = (const float*)d_in[5];
    const float* bk    = (const float*)d_in[6];
    const float* Wv    = (const float*)d_in[7];
    const float* bv    = (const float*)d_in[8];
    const float* Wo    = (const float*)d_in[9];
    const float* bo    = (const float*)d_in[10];
    float* out = (float*)d_out;

    const int ctx_smem = 2 * (256 + 64) * CSTRIDE * 2;
    cudaFuncSetAttribute(proj_hgemm, cudaFuncAttributeMaxDynamicSharedMemorySize, PROJ_SMEM);
    cudaFuncSetAttribute(out_hgemm,  cudaFuncAttributeMaxDynamicSharedMemorySize, PROJ_SMEM);
    cudaFuncSetAttribute(ctx_hgemm,  cudaFuncAttributeMaxDynamicSharedMemorySize, ctx_smem);

    cvt_x<<<dim3(8192, 1, 3), 256>>>(query, key_, value);
    cvt_w<<<dim3(16, 16, 3), 256>>>(Wq, Wk, Wv);
    cvt_wo<<<1024, 256>>>(Wo);
    proj_hgemm<<<dim3(8, 64, 3), 256, PROJ_SMEM>>>(bq, bk, bv);
    scores_hmma<<<dim3(16, 16, 64), 256>>>();
    recip_kernel<<<512, 256>>>();
    v2h_fold<<<dim3(32, 64), 256>>>();
    ctx_hgemm<<<dim3(8, 64), 256, ctx_smem>>>();
    out_hgemm<<<dim3(8, 64), 256, PROJ_SMEM>>>(bo, out);
}